// round 11
// baseline (speedup 1.0000x reference)
#include <cuda_runtime.h>
#include <cuda_bf16.h>
#include <cstdint>

// ---------------------------------------------------------------------------
// Problem constants
// ---------------------------------------------------------------------------
#define CB   8
#define CL   512
#define CM   512
#define CH   8
#define CDK  128
#define CDV  128
#define CS   512
#define CDM  1024
#define CW   1024   // W_REC
#define NBH  64
#define NROWS 4096
#define SCW  1536   // W + S

static __device__ __constant__ const float TAUI = 0.08838834764831845f; // 1/sqrt(128)

typedef __nv_bfloat16 bf16;

// ---------------------------------------------------------------------------
// Scratch
// ---------------------------------------------------------------------------
__device__ float g_proj  [(size_t)NROWS * 4096];   // qraw | k | v | g (fused proj out)
__device__ float g_vv    [(size_t)NBH * CL * CDV];
__device__ float g_gate  [(size_t)NROWS * CDM];
__device__ float g_rbd   [(size_t)NBH * CL * CW];
__device__ unsigned long long g_zpk[NBH * CL];
__device__ float g_csq   [CH * CS];
__device__ int   g_unit_ctr;

__device__ bf16 g_xt_h   [(size_t)NROWS * CDM];
__device__ bf16 g_xt_l   [(size_t)NROWS * CDM];
__device__ bf16 g_wall_h [(size_t)4096 * 1024];   // Wq^T (rows 0-1023) | Wkvg^T (1024-4095)
__device__ bf16 g_wall_l [(size_t)4096 * 1024];
__device__ bf16 g_wrest_h[(size_t)1024 * 1024];
__device__ bf16 g_wrest_l[(size_t)1024 * 1024];
__device__ bf16 g_qu_h   [(size_t)NBH * CL * CDK];
__device__ bf16 g_qu_l   [(size_t)NBH * CL * CDK];
__device__ bf16 g_qv_h   [(size_t)NBH * CL * CDK];
__device__ bf16 g_qv_l   [(size_t)NBH * CL * CDK];
__device__ bf16 g_kl_h   [(size_t)NBH * CL * CDK];
__device__ bf16 g_kl_l   [(size_t)NBH * CL * CDK];
__device__ bf16 g_khat_h [(size_t)NBH * CM * CDK];
__device__ bf16 g_khat_l [(size_t)NBH * CM * CDK];
__device__ bf16 g_cb_h   [(size_t)CH * CS * CDK];
__device__ bf16 g_cb_l   [(size_t)CH * CS * CDK];
__device__ bf16 g_xlr_h  [(size_t)CH * CW * CDK];
__device__ bf16 g_xlr_l  [(size_t)CH * CW * CDK];
__device__ bf16 g_vt_h   [(size_t)NBH * CDV * SCW];
__device__ bf16 g_vt_l   [(size_t)NBH * CDV * SCW];
__device__ bf16 g_wvg_h  [(size_t)NROWS * CDM];
__device__ bf16 g_wvg_l  [(size_t)NROWS * CDM];

// ---------------------------------------------------------------------------
// primitives
// ---------------------------------------------------------------------------
__device__ __forceinline__ uint32_t cvta_s(const void* p) {
    return (uint32_t)__cvta_generic_to_shared(p);
}
__device__ __forceinline__ void ldmx4(uint32_t addr, uint32_t& r0, uint32_t& r1,
                                      uint32_t& r2, uint32_t& r3) {
    asm volatile("ldmatrix.sync.aligned.m8n8.x4.shared.b16 {%0,%1,%2,%3}, [%4];"
                 : "=r"(r0), "=r"(r1), "=r"(r2), "=r"(r3) : "r"(addr));
}
__device__ __forceinline__ void mma16816(float c[4], const uint32_t a[4], const uint32_t b[2]) {
    asm volatile(
        "mma.sync.aligned.m16n8k16.row.col.f32.bf16.bf16.f32 "
        "{%0,%1,%2,%3}, {%4,%5,%6,%7}, {%8,%9}, {%0,%1,%2,%3};"
        : "+f"(c[0]), "+f"(c[1]), "+f"(c[2]), "+f"(c[3])
        : "r"(a[0]), "r"(a[1]), "r"(a[2]), "r"(a[3]), "r"(b[0]), "r"(b[1]));
}
__device__ __forceinline__ void cpa16(uint32_t d, const void* s) {
    asm volatile("cp.async.ca.shared.global [%0], [%1], 16;" :: "r"(d), "l"(s));
}
__device__ __forceinline__ void cpa_commit() {
    asm volatile("cp.async.commit_group;");
}
template <int NN>
__device__ __forceinline__ void cpa_wait() {
    asm volatile("cp.async.wait_group %0;" :: "n"(NN));
}

__device__ __forceinline__ void splitw(float x, bf16* h, bf16* l) {
    bf16 hh = __float2bfloat16_rn(x);
    *h = hh;
    *l = __float2bfloat16_rn(x - __bfloat162float(hh));
}
__device__ __forceinline__ void split4(float4 v, bf16* hp, bf16* lp) {
    __nv_bfloat162 h0 = __floats2bfloat162_rn(v.x, v.y);
    __nv_bfloat162 h1 = __floats2bfloat162_rn(v.z, v.w);
    float2 f0 = __bfloat1622float2(h0);
    float2 f1 = __bfloat1622float2(h1);
    __nv_bfloat162 l0 = __floats2bfloat162_rn(v.x - f0.x, v.y - f0.y);
    __nv_bfloat162 l1 = __floats2bfloat162_rn(v.z - f1.x, v.w - f1.y);
    uint2 hv, lv;
    hv.x = *(uint32_t*)&h0; hv.y = *(uint32_t*)&h1;
    lv.x = *(uint32_t*)&l0; lv.y = *(uint32_t*)&l1;
    *(uint2*)hp = hv;
    *(uint2*)lp = lv;
}
__device__ __forceinline__ uint32_t packbf(float x, float y) {
    __nv_bfloat162 t = __floats2bfloat162_rn(x, y);
    return *(uint32_t*)&t;
}
__device__ __forceinline__ uint32_t packbf_res(float x, float y, uint32_t hp) {
    __nv_bfloat162 hv = *(__nv_bfloat162*)&hp;
    float2 f = __bfloat1622float2(hv);
    return packbf(x - f.x, y - f.y);
}

// ---------------------------------------------------------------------------
// reductions
// ---------------------------------------------------------------------------
__device__ __forceinline__ float block_sum(float v) {
    __shared__ float sb_[8];
    int tid = threadIdx.x;
    int nw  = blockDim.x >> 5;
    #pragma unroll
    for (int o = 16; o; o >>= 1) v += __shfl_down_sync(0xffffffffu, v, o);
    __syncthreads();
    if ((tid & 31) == 0) sb_[tid >> 5] = v;
    __syncthreads();
    float r = 0.f;
    for (int i = 0; i < nw; ++i) r += sb_[i];
    return r;
}
__device__ __forceinline__ float warp_sum(float v) {
    #pragma unroll
    for (int o = 16; o; o >>= 1) v += __shfl_xor_sync(0xffffffffu, v, o);
    return v;
}

// ---------------------------------------------------------------------------
// Fused preprocessing (one launch)
// ---------------------------------------------------------------------------
#define PS0 1024                 // Wq transpose  -> wall rows 0-1023
#define PS1 (PS0 + 3072)         // Wkvg transpose -> wall rows 1024-4095
#define PS2 (PS1 + 1024)         // Wres transpose
#define PS3 (PS2 + 4096)         // khat convert
#define PS4 (PS3 + 512)          // cb convert
#define PS5 (PS4 + 1024)         // xlr convert
#define PS6 (PS5 + 4096)         // LN rows
#define PS7 (PS6 + 512)          // csq (8 rows/block)
#define PS8 (PS7 + 32)           // zinit
#define PREP_GRID PS8

__device__ __forceinline__ void do_transpose(const float* __restrict__ src,
                                             bf16* __restrict__ dh,
                                             bf16* __restrict__ dl,
                                             int R, int C, int id,
                                             float (*tile)[33]) {
    int bx = id % (C >> 5), by = id / (C >> 5);
    int c0 = bx * 32, r0 = by * 32;
    int x = threadIdx.x & 31, y = (threadIdx.x >> 5) * 4;
    #pragma unroll
    for (int i = 0; i < 4; ++i)
        tile[y + i][x] = src[(size_t)(r0 + y + i) * C + c0 + x];
    __syncthreads();
    #pragma unroll
    for (int i = 0; i < 4; ++i) {
        size_t o = (size_t)(c0 + y + i) * R + r0 + x;
        splitw(tile[x][y + i], dh + o, dl + o);
    }
}
__device__ __forceinline__ void do_convert(const float* __restrict__ src,
                                           bf16* __restrict__ h,
                                           bf16* __restrict__ l, int id) {
    size_t idx = (size_t)id * 256 + threadIdx.x;
    float4 v = ((const float4*)src)[idx];
    split4(v, h + idx * 4, l + idx * 4);
}

__global__ void __launch_bounds__(256) prep_kernel(
    const float* __restrict__ W_q, const float* __restrict__ W_kvg,
    const float* __restrict__ W_res,
    const float* __restrict__ xl_k_hat, const float* __restrict__ codebook,
    const float* __restrict__ xl_r, const float* __restrict__ input,
    bf16* wall_h, bf16* wall_l, bf16* wrest_h, bf16* wrest_l,
    bf16* khat_h, bf16* khat_l, bf16* cb_h, bf16* cb_l,
    bf16* xlr_h, bf16* xlr_l, bf16* xt_h, bf16* xt_l,
    float* csq, unsigned long long* zpk, int* ctr) {

    __shared__ float tile[32][33];
    int bid = blockIdx.x;
    int tid = threadIdx.x;

    if (bid < PS0) {
        do_transpose(W_q, wall_h, wall_l, 1024, 1024, bid, tile);
    } else if (bid < PS1) {
        do_transpose(W_kvg, wall_h + (size_t)1024 * 1024, wall_l + (size_t)1024 * 1024,
                     1024, 3072, bid - PS0, tile);
    } else if (bid < PS2) {
        do_transpose(W_res, wrest_h, wrest_l, 1024, 1024, bid - PS1, tile);
    } else if (bid < PS3) {
        do_convert(xl_k_hat, khat_h, khat_l, bid - PS2);
    } else if (bid < PS4) {
        do_convert(codebook, cb_h, cb_l, bid - PS3);
    } else if (bid < PS5) {
        do_convert(xl_r, xlr_h, xlr_l, bid - PS4);
    } else if (bid < PS6) {
        int row = bid - PS5;
        const float* xr = input + (size_t)row * CDM;
        float4 v = *(const float4*)(xr + tid * 4);
        float s = v.x + v.y + v.z + v.w;
        float mu = block_sum(s) * (1.f / 1024.f);
        v.x -= mu; v.y -= mu; v.z -= mu; v.w -= mu;
        float s2 = v.x * v.x + v.y * v.y + v.z * v.z + v.w * v.w;
        float rstd = rsqrtf(block_sum(s2) * (1.f / 1024.f) + 1e-6f);
        v.x *= rstd; v.y *= rstd; v.z *= rstd; v.w *= rstd;
        split4(v, xt_h + (size_t)row * CDM + tid * 4, xt_l + (size_t)row * CDM + tid * 4);
    } else if (bid < PS7) {
        int wid  = tid >> 5, lane = tid & 31;
        int row = (bid - PS6) * 8 + wid;
        float4 v = *(const float4*)(codebook + (size_t)row * CDK + lane * 4);
        float s = warp_sum(v.x * v.x + v.y * v.y + v.z * v.z + v.w * v.w);
        if (lane == 0) csq[row] = s;
    } else {
        int id = bid - PS7;
        size_t base = (size_t)id * 1024 + tid * 4;
        zpk[base + 0] = ~0ull; zpk[base + 1] = ~0ull;
        zpk[base + 2] = ~0ull; zpk[base + 3] = ~0ull;
        if (id == 0 && tid == 0) *ctr = 0;
    }
}

// ---------------------------------------------------------------------------
// per-(b,l,h) transform (reads fused proj buffer)
// ---------------------------------------------------------------------------
__global__ void __launch_bounds__(256) transform_kernel(const float* __restrict__ proj,
                                                        const float* __restrict__ x_u,
                                                        const float* __restrict__ x_v,
                                                        bf16* __restrict__ quh, bf16* __restrict__ qul,
                                                        bf16* __restrict__ qvh, bf16* __restrict__ qvl,
                                                        bf16* __restrict__ klh, bf16* __restrict__ kll,
                                                        float* __restrict__ vv,
                                                        float* __restrict__ gate) {
    int wid  = threadIdx.x >> 5;
    int lane = threadIdx.x & 31;
    int idx = blockIdx.x * 8 + wid;
    int h  = idx & 7;
    int bl = idx >> 3;
    int b = bl >> 9, l = bl & 511;
    int d0 = lane * 4;
    const float* prow = proj + (size_t)bl * 4096 + h * CDK + d0;

    float4 q = *(const float4*)(prow);
    float mu = warp_sum(q.x + q.y + q.z + q.w) * (1.f / 128.f);
    q.x -= mu; q.y -= mu; q.z -= mu; q.w -= mu;
    float var = warp_sum(q.x * q.x + q.y * q.y + q.z * q.z + q.w * q.w) * (1.f / 128.f);
    float rs = rsqrtf(var + 1e-6f);
    float4 xu = *(const float4*)(x_u + h * CDK + d0);
    float4 xv = *(const float4*)(x_v + h * CDK + d0);
    size_t o = (((size_t)b * CH + h) * CL + l) * CDK + d0;
    split4(make_float4(q.x * rs + xu.x, q.y * rs + xu.y, q.z * rs + xu.z, q.w * rs + xu.w),
           quh + o, qul + o);
    split4(make_float4(q.x * rs + xv.x, q.y * rs + xv.y, q.z * rs + xv.z, q.w * rs + xv.w),
           qvh + o, qvl + o);

    float4 k = *(const float4*)(prow + 1024);
    float kmu = warp_sum(k.x + k.y + k.z + k.w) * (1.f / 128.f);
    k.x -= kmu; k.y -= kmu; k.z -= kmu; k.w -= kmu;
    float kvar = warp_sum(k.x * k.x + k.y * k.y + k.z * k.z + k.w * k.w) * (1.f / 128.f);
    float krs = rsqrtf(kvar + 1e-6f);
    split4(make_float4(k.x * krs, k.y * krs, k.z * krs, k.w * krs), klh + o, kll + o);

    *(float4*)(vv + o) = *(const float4*)(prow + 2048);

    float4 gg = *(const float4*)(prow + 3072);
    float4 gs;
    gs.x = gg.x / (1.f + __expf(-gg.x));
    gs.y = gg.y / (1.f + __expf(-gg.y));
    gs.z = gg.z / (1.f + __expf(-gg.z));
    gs.w = gg.w / (1.f + __expf(-gg.w));
    *(float4*)(gate + (size_t)bl * CDM + h * CDK + d0) = gs;
}

// ---------------------------------------------------------------------------
// NT tensor-core GEMM body (bf16x3, 3-stage cp.async). MODE: 0=BD, 3=VQ, 4=PROJ
// smem buffer: >= 73728 bytes
// ---------------------------------------------------------------------------
#define STG_B 12288
#define CMP_B 6144
#define SBOFF 36864
template <int MODE>
__device__ __forceinline__ void gemm_body(
    char* smem, int bm, int bn, int bh,
    const bf16* __restrict__ Ah, const bf16* __restrict__ Al,
    const bf16* __restrict__ Bh, const bf16* __restrict__ Bl,
    const float* __restrict__ csq,
    unsigned long long* zpk_out,
    float* __restrict__ outp,
    int N, int K, int lda) {

    int tid  = threadIdx.x;
    int lane = tid & 31, warp = tid >> 5;
    int wm = warp >> 2, wn = warp & 3;
    int h  = bh & 7;

    // BD dead-tile skip
    if (MODE == 0 && (bn + bm) < 257) return;

    size_t aoff = (MODE == 4) ? 0 : (size_t)bh * CL * CDK;

    int srow = tid >> 1;
    int sc8  = (tid & 1) * 8;
    const bf16* a_h = Ah + aoff + (size_t)(bm + srow) * lda + sc8;
    const bf16* a_l = Al + aoff + (size_t)(bm + srow) * lda + sc8;
    const bf16 *b_h, *b_l;
    {
        int n = bn + srow;
        size_t boff;
        if (MODE == 0)      boff = ((size_t)h * CW + n) * CDK;
        else if (MODE == 3) boff = ((size_t)h * CS + n) * CDK;
        else                boff = (size_t)n * K;
        b_h = Bh + boff + sc8; b_l = Bl + boff + sc8;
    }

    uint32_t sA = cvta_s(smem);
    uint32_t sB = sA + SBOFF;
    uint32_t dA = sA + (uint32_t)(srow * 24 + sc8) * 2;
    uint32_t dB = sB + (uint32_t)(srow * 24 + sc8) * 2;

    int a_off = (wm * 64 + (lane & 15)) * 24 + ((lane >> 4) << 3);
    int b_off = (wn * 32 + ((lane >> 4) << 3) + (lane & 7)) * 24 + (((lane >> 3) & 1) << 3);

    float acc[4][4][4] = {};
    int T = K >> 4;

    cpa16(dA,         a_h);  cpa16(dA + CMP_B, a_l);
    cpa16(dB,         b_h);  cpa16(dB + CMP_B, b_l);
    cpa_commit();

    #pragma unroll 1
    for (int kt = 0; kt < T; ++kt) {
        if (kt + 1 < T) {
            int st = (kt + 1) % 3;
            int k0 = (kt + 1) * 16;
            cpa16(dA + st * STG_B,         a_h + k0);
            cpa16(dA + st * STG_B + CMP_B, a_l + k0);
            cpa16(dB + st * STG_B,         b_h + k0);
            cpa16(dB + st * STG_B + CMP_B, b_l + k0);
            cpa_commit();
            cpa_wait<1>();
        } else {
            cpa_wait<0>();
        }
        __syncthreads();

        int cs = kt % 3;
        uint32_t aH = sA + cs * STG_B + (uint32_t)a_off * 2;
        uint32_t bH = sB + cs * STG_B + (uint32_t)b_off * 2;
        uint32_t ah[4][4], al[4][4], bhf[4][2], blf[4][2];
        #pragma unroll
        for (int t = 0; t < 4; ++t) {
            ldmx4(aH + t * 768,         ah[t][0], ah[t][1], ah[t][2], ah[t][3]);
            ldmx4(aH + CMP_B + t * 768, al[t][0], al[t][1], al[t][2], al[t][3]);
        }
        #pragma unroll
        for (int u2 = 0; u2 < 2; ++u2) {
            uint32_t r0, r1, r2, r3;
            ldmx4(bH + u2 * 768, r0, r1, r2, r3);
            bhf[2 * u2][0] = r0; bhf[2 * u2][1] = r1;
            bhf[2 * u2 + 1][0] = r2; bhf[2 * u2 + 1][1] = r3;
            ldmx4(bH + CMP_B + u2 * 768, r0, r1, r2, r3);
            blf[2 * u2][0] = r0; blf[2 * u2][1] = r1;
            blf[2 * u2 + 1][0] = r2; blf[2 * u2 + 1][1] = r3;
        }
        #pragma unroll
        for (int t = 0; t < 4; ++t)
            #pragma unroll
            for (int u = 0; u < 4; ++u) {
                mma16816(acc[t][u], ah[t], bhf[u]);
                mma16816(acc[t][u], ah[t], blf[u]);
                mma16816(acc[t][u], al[t], bhf[u]);
            }
    }

    int g  = lane >> 2;
    int qd = lane & 3;

    if constexpr (MODE == 4) {
        #pragma unroll
        for (int t = 0; t < 4; ++t) {
            int r = bm + wm * 64 + t * 16 + g;
            #pragma unroll
            for (int u = 0; u < 4; ++u) {
                int c = bn + wn * 32 + u * 8 + qd * 2;
                *(float2*)(outp + (size_t)r * N + c) =
                    make_float2(acc[t][u][0], acc[t][u][1]);
                *(float2*)(outp + (size_t)(r + 8) * N + c) =
                    make_float2(acc[t][u][2], acc[t][u][3]);
            }
        }
    } else if constexpr (MODE == 0) {
        #pragma unroll
        for (int t = 0; t < 4; ++t) {
            int l = bm + wm * 64 + t * 16 + g;
            #pragma unroll
            for (int u = 0; u < 4; ++u) {
                int c = bn + wn * 32 + u * 8 + qd * 2;
                *(float2*)(outp + ((size_t)bh * CL + l) * CW + c) =
                    make_float2(acc[t][u][0] * TAUI, acc[t][u][1] * TAUI);
                *(float2*)(outp + ((size_t)bh * CL + l + 8) * CW + c) =
                    make_float2(acc[t][u][2] * TAUI, acc[t][u][3] * TAUI);
            }
        }
    } else {   // MODE 3: VQ argmin
        unsigned long long* zmin = reinterpret_cast<unsigned long long*>(smem);
        __syncthreads();
        if (tid < 128) zmin[tid] = ~0ull;
        __syncthreads();
        #pragma unroll
        for (int t = 0; t < 4; ++t) {
            unsigned long long b0 = ~0ull, b1 = ~0ull;
            #pragma unroll
            for (int u = 0; u < 4; ++u) {
                #pragma unroll
                for (int p = 0; p < 2; ++p) {
                    int s = bn + wn * 32 + u * 8 + qd * 2 + p;
                    float cs = csq[h * CS + s];
                    {
                        float val = cs - 2.f * acc[t][u][p];
                        unsigned uu = __float_as_uint(val);
                        uu = (uu & 0x80000000u) ? ~uu : (uu | 0x80000000u);
                        unsigned long long key = ((unsigned long long)uu << 32) | (unsigned)s;
                        if (key < b0) b0 = key;
                    }
                    {
                        float val = cs - 2.f * acc[t][u][2 + p];
                        unsigned uu = __float_as_uint(val);
                        uu = (uu & 0x80000000u) ? ~uu : (uu | 0x80000000u);
                        unsigned long long key = ((unsigned long long)uu << 32) | (unsigned)s;
                        if (key < b1) b1 = key;
                    }
                }
            }
            unsigned long long o;
            o = __shfl_xor_sync(0xffffffffu, b0, 1); if (o < b0) b0 = o;
            o = __shfl_xor_sync(0xffffffffu, b0, 2); if (o < b0) b0 = o;
            o = __shfl_xor_sync(0xffffffffu, b1, 1); if (o < b1) b1 = o;
            o = __shfl_xor_sync(0xffffffffu, b1, 2); if (o < b1) b1 = o;
            if (qd == 0) {
                atomicMin(&zmin[wm * 64 + t * 16 + g], b0);
                atomicMin(&zmin[wm * 64 + t * 16 + g + 8], b1);
            }
        }
        __syncthreads();
        if (tid < 128)
            atomicMin(&zpk_out[(size_t)bh * CL + bm + tid], zmin[tid]);
    }
}

// plain GEMM kernel (proj / output proj)
__global__ void __launch_bounds__(256) mma_gemm4_kernel(
    const bf16* __restrict__ Ah, const bf16* __restrict__ Al,
    const bf16* __restrict__ Bh, const bf16* __restrict__ Bl,
    float* __restrict__ outp, int N, int K, int lda) {
    __shared__ __align__(16) char smem[73728];
    gemm_body<4>(smem, blockIdx.y * 128, blockIdx.x * 128, 0,
                 Ah, Al, Bh, Bl, nullptr, nullptr, outp, N, K, lda);
}

// ---------------------------------------------------------------------------
// Merged mid-stage kernel: VQ GEMM + BD GEMM + vt gather-transpose
// blocks [0,1024): VQ, [1024,3072): BD, [3072,15360): vt
// ---------------------------------------------------------------------------
#define MID_VQ   1024
#define MID_BD   3072
#define MID_END  15360
__global__ void __launch_bounds__(256) mid_kernel(
    const bf16* __restrict__ kl_h, const bf16* __restrict__ kl_l,
    const bf16* __restrict__ qv_h, const bf16* __restrict__ qv_l,
    const bf16* __restrict__ cb_h, const bf16* __restrict__ cb_l,
    const bf16* __restrict__ xlr_h, const bf16* __restrict__ xlr_l,
    const float* __restrict__ csq,
    unsigned long long* __restrict__ zpk,
    float* __restrict__ rbd,
    const float* __restrict__ xl_v, const float* __restrict__ vv,
    const float* __restrict__ aggu,
    bf16* __restrict__ vth, bf16* __restrict__ vtl) {

    __shared__ __align__(16) char smem[73728];
    int bid = blockIdx.x;

    if (bid < MID_VQ) {
        int x = bid & 3, y = (bid >> 2) & 3, z = bid >> 4;
        gemm_body<3>(smem, y * 128, x * 128, z, kl_h, kl_l, cb_h, cb_l,
                     csq, zpk, nullptr, 512, 128, 128);
    } else if (bid < MID_BD) {
        int id = bid - MID_VQ;
        int x = id & 7, y = (id >> 3) & 3, z = id >> 5;
        gemm_body<0>(smem, y * 128, x * 128, z, qv_h, qv_l, xlr_h, xlr_l,
                     nullptr, nullptr, rbd, 1024, 128, 128);
    } else {
        int id = bid - MID_BD;
        int wx = id % 48, vy = (id / 48) & 3, zb = id / 192;
        float (*tile)[33] = reinterpret_cast<float (*)[33]>(smem);
        int w0 = wx * 32, v0 = vy * 32;
        int x = threadIdx.x & 31, y = (threadIdx.x >> 5) * 4;
        #pragma unroll
        for (int i = 0; i < 4; ++i) {
            int w = w0 + y + i;
            const float* srcrow;
            if (w < CM)      srcrow = xl_v + ((size_t)zb * CM + w) * CDV;
            else if (w < CW) srcrow = vv   + ((size_t)zb * CL + (w - CM)) * CDV;
            else             srcrow = aggu + ((size_t)zb * CS + (w - CW)) * CDV;
            tile[y + i][x] = srcrow[v0 + x];
        }
        __syncthreads();
        #pragma unroll
        for (int i = 0; i < 4; ++i) {
            size_t o = ((size_t)zb * CDV + v0 + y + i) * SCW + w0 + x;
            splitw(tile[x][y + i], vth + o, vtl + o);
        }
    }
}

// ---------------------------------------------------------------------------
// Fused attention (persistent, work-stealing): scores + online softmax + P@V
// ---------------------------------------------------------------------------
#define APITCH 272
#define APLANE 34816
#define ABUF   69632
#define NUNITS 256
__global__ void __launch_bounds__(256) attn_kernel(
    const bf16* __restrict__ quh, const bf16* __restrict__ qul,
    const bf16* __restrict__ khat_h, const bf16* __restrict__ khat_l,
    const bf16* __restrict__ cb_h, const bf16* __restrict__ cb_l,
    const bf16* __restrict__ vt_h, const bf16* __restrict__ vt_l,
    const unsigned long long* __restrict__ zpk,
    const float* __restrict__ rbd,
    const float* __restrict__ agg_lower,
    const float* __restrict__ gate,
    int* __restrict__ unit_ctr,
    bf16* __restrict__ outh, bf16* __restrict__ outl) {

    extern __shared__ __align__(16) char smem_raw[];
    uint32_t sQU = cvta_s(smem_raw);
    uint32_t sKT = sQU + ABUF;
    uint32_t sVT = sQU + 2 * ABUF;
    __shared__ int s_unit;

    int tid  = threadIdx.x;
    int lane = tid & 31, warp = tid >> 5;
    int g = lane >> 2, qd = lane & 3;

    for (;;) {
        __syncthreads();
        if (tid == 0) s_unit = atomicAdd(unit_ctr, 1);
        __syncthreads();
        int unit = s_unit;
        if (unit >= NUNITS) break;

        int bm = (unit >> 6) * 128;
        int bh = unit & 63;
        int h  = bh & 7;
        int b  = bh >> 3;

        int tiles[12]; int nt = 0;
        #pragma unroll
        for (int j = 0; j < 12; ++j)
            if (!(j < 8 && j * 128 >= bm + CM + 128)) tiles[nt++] = j;

        auto load_qu = [&]() {
            size_t qoff = (size_t)bh * CL * CDK;
            #pragma unroll
            for (int i = 0; i < 8; ++i) {
                int id = tid + i * 256;
                int r = id >> 4, c = id & 15;
                uint32_t d = sQU + r * APITCH + c * 16;
                cpa16(d,          quh + qoff + (size_t)(bm + r) * CDK + c * 8);
                cpa16(d + APLANE, qul + qoff + (size_t)(bm + r) * CDK + c * 8);
            }
        };
        auto load_kt = [&](int j) {
            #pragma unroll
            for (int i = 0; i < 8; ++i) {
                int id = tid + i * 256;
                int r = id >> 4, c = id & 15;
                int n = j * 128 + r;
                const bf16 *sh, *sl;
                if (j < 4) {
                    size_t o = ((size_t)bh * CM + n) * CDK;
                    sh = khat_h + o; sl = khat_l + o;
                } else if (j < 8) {
                    unsigned zi = (unsigned)(zpk[(size_t)bh * CL + (n - CM)] & 0xffffffffull);
                    size_t o = ((size_t)h * CS + zi) * CDK;
                    sh = cb_h + o; sl = cb_l + o;
                } else {
                    size_t o = ((size_t)h * CS + (n - CW)) * CDK;
                    sh = cb_h + o; sl = cb_l + o;
                }
                uint32_t d = sKT + r * APITCH + c * 16;
                cpa16(d,          sh + c * 8);
                cpa16(d + APLANE, sl + c * 8);
            }
        };
        auto load_vt = [&](int j) {
            #pragma unroll
            for (int i = 0; i < 8; ++i) {
                int id = tid + i * 256;
                int r = id >> 4, c = id & 15;
                size_t o = ((size_t)bh * CDV + r) * SCW + j * 128 + c * 8;
                uint32_t d = sVT + r * APITCH + c * 16;
                cpa16(d,          vt_h + o);
                cpa16(d + APLANE, vt_l + o);
            }
        };

        uint32_t quB = sQU + (uint32_t)(warp * 16 + (lane & 15)) * APITCH + ((lane >> 4) << 4);
        uint32_t bB  = (uint32_t)((((lane >> 4) << 3) + (lane & 7)) * APITCH) + (((lane >> 3) & 1) << 4);

        int l0 = bm + warp * 16 + g;
        int l1 = l0 + 8;

        float O[16][4] = {};
        float m0 = -3.4e38f, m1 = -3.4e38f, d0 = 0.f, d1 = 0.f;

        load_qu();
        load_kt(tiles[0]);
        cpa_commit();

        #pragma unroll 1
        for (int ti = 0; ti < nt; ++ti) {
            int j = tiles[ti];
            cpa_wait<0>();
            __syncthreads();
            load_vt(j);
            cpa_commit();

            float S[16][4] = {};
            #pragma unroll
            for (int kg = 0; kg < 8; ++kg) {
                uint32_t ah[4], al[4];
                ldmx4(quB + kg * 32,          ah[0], ah[1], ah[2], ah[3]);
                ldmx4(quB + APLANE + kg * 32, al[0], al[1], al[2], al[3]);
                #pragma unroll
                for (int nf = 0; nf < 8; ++nf) {
                    uint32_t base = sKT + bB + nf * (16 * APITCH) + kg * 32;
                    uint32_t p0, p1, p2, p3, q0, q1, q2, q3;
                    ldmx4(base,          p0, p1, p2, p3);
                    ldmx4(base + APLANE, q0, q1, q2, q3);
                    uint32_t bp[2], bq[2];
                    bp[0] = p0; bp[1] = p1; bq[0] = q0; bq[1] = q1;
                    mma16816(S[nf * 2], ah, bp);
                    mma16816(S[nf * 2], ah, bq);
                    mma16816(S[nf * 2], al, bp);
                    bp[0] = p2; bp[1] = p3; bq[0] = q2; bq[1] = q3;
                    mma16816(S[nf * 2 + 1], ah, bp);
                    mma16816(S[nf * 2 + 1], ah, bq);
                    mma16816(S[nf * 2 + 1], al, bp);
                }
            }

            if (j < 8) {
                const float* rr0 = rbd + ((size_t)bh * CL + l0) * CW + (CL - 1) - l0;
                const float* rr1 = rbd + ((size_t)bh * CL + l1) * CW + (CL - 1) - l1;
                int wb = j * 128 + qd * 2;
                #pragma unroll
                for (int u = 0; u < 16; ++u) {
                    int w = wb + u * 8;
                    S[u][0] = (w     <= l0 + CM) ? S[u][0] * TAUI + rr0[w]     : -1e30f;
                    S[u][1] = (w + 1 <= l0 + CM) ? S[u][1] * TAUI + rr0[w + 1] : -1e30f;
                    S[u][2] = (w     <= l1 + CM) ? S[u][2] * TAUI + rr1[w]     : -1e30f;
                    S[u][3] = (w + 1 <= l1 + CM) ? S[u][3] * TAUI + rr1[w + 1] : -1e30f;
                }
            } else {
                int sb = (j - 8) * 128 + qd * 2;
                #pragma unroll
                for (int u = 0; u < 16; ++u) {
                    int s = sb + u * 8;
                    float a0 = agg_lower[(size_t)bh * CS + s];
                    float a1 = agg_lower[(size_t)bh * CS + s + 1];
                    float b0 = (a0 > 0.f) ? logf(fmaxf(a0, 1e-30f)) : -1e30f;
                    float b1 = (a1 > 0.f) ? logf(fmaxf(a1, 1e-30f)) : -1e30f;
                    S[u][0] = S[u][0] * TAUI + b0;
                    S[u][1] = S[u][1] * TAUI + b1;
                    S[u][2] = S[u][2] * TAUI + b0;
                    S[u][3] = S[u][3] * TAUI + b1;
                }
            }

            float mx0 = -3.4e38f, mx1 = -3.4e38f;
            #pragma unroll
            for (int u = 0; u < 16; ++u) {
                mx0 = fmaxf(mx0, fmaxf(S[u][0], S[u][1]));
                mx1 = fmaxf(mx1, fmaxf(S[u][2], S[u][3]));
            }
            mx0 = fmaxf(mx0, __shfl_xor_sync(0xffffffffu, mx0, 1));
            mx0 = fmaxf(mx0, __shfl_xor_sync(0xffffffffu, mx0, 2));
            mx1 = fmaxf(mx1, __shfl_xor_sync(0xffffffffu, mx1, 1));
            mx1 = fmaxf(mx1, __shfl_xor_sync(0xffffffffu, mx1, 2));
            float nm0 = fmaxf(m0, mx0), nm1 = fmaxf(m1, mx1);
            float al0 = __expf(m0 - nm0), al1 = __expf(m1 - nm1);
            m0 = nm0; m1 = nm1;
            float s0 = 0.f, s1 = 0.f;
            #pragma unroll
            for (int u = 0; u < 16; ++u) {
                S[u][0] = __expf(S[u][0] - m0);
                S[u][1] = __expf(S[u][1] - m0);
                S[u][2] = __expf(S[u][2] - m1);
                S[u][3] = __expf(S[u][3] - m1);
                s0 += S[u][0] + S[u][1];
                s1 += S[u][2] + S[u][3];
            }
            s0 += __shfl_xor_sync(0xffffffffu, s0, 1);
            s0 += __shfl_xor_sync(0xffffffffu, s0, 2);
            s1 += __shfl_xor_sync(0xffffffffu, s1, 1);
            s1 += __shfl_xor_sync(0xffffffffu, s1, 2);
            d0 = d0 * al0 + s0;
            d1 = d1 * al1 + s1;
            #pragma unroll
            for (int u = 0; u < 16; ++u) {
                O[u][0] *= al0; O[u][1] *= al0;
                O[u][2] *= al1; O[u][3] *= al1;
            }

            cpa_wait<0>();
            __syncthreads();
            if (ti + 1 < nt) { load_kt(tiles[ti + 1]); cpa_commit(); }

            #pragma unroll
            for (int kg = 0; kg < 8; ++kg) {
                int u2 = kg * 2;
                uint32_t pah[4], pal[4];
                pah[0] = packbf(S[u2][0], S[u2][1]);
                pah[1] = packbf(S[u2][2], S[u2][3]);
                pah[2] = packbf(S[u2 + 1][0], S[u2 + 1][1]);
                pah[3] = packbf(S[u2 + 1][2], S[u2 + 1][3]);
                pal[0] = packbf_res(S[u2][0], S[u2][1], pah[0]);
                pal[1] = packbf_res(S[u2][2], S[u2][3], pah[1]);
                pal[2] = packbf_res(S[u2 + 1][0], S[u2 + 1][1], pah[2]);
                pal[3] = packbf_res(S[u2 + 1][2], S[u2 + 1][3], pah[3]);
                #pragma unroll
                for (int nf = 0; nf < 8; ++nf) {
                    uint32_t base = sVT + bB + nf * (16 * APITCH) + kg * 32;
                    uint32_t p0, p1, p2, p3, q0, q1, q2, q3;
                    ldmx4(base,          p0, p1, p2, p3);
                    ldmx4(base + APLANE, q0, q1, q2, q3);
                    uint32_t bp[2], bq[2];
                    bp[0] = p0; bp[1] = p1; bq[0] = q0; bq[1] = q1;
                    mma16816(O[nf * 2], pah, bp);
                    mma16816(O[nf * 2], pah, bq);
                    mma16816(O[nf * 2], pal, bp);
                    bp[0] = p2; bp[1] = p3; bq[0] = q2; bq[1] = q3;
                    mma16816(O[nf * 2 + 1], pah, bp);
                    mma16816(O[nf * 2 + 1], pah, bq);
                    mma16816(O[nf * 2 + 1], pal, bp);
                }
            }
        }

        float i0 = 1.f / d0, i1 = 1.f / d1;
        #pragma unroll
        for (int u = 0; u < 16; ++u) {
            int c = (u << 3) + qd * 2;
            size_t o0 = ((size_t)b * CL + l0) * CDM + h * CDV + c;
            size_t o1 = ((size_t)b * CL + l1) * CDM + h * CDV + c;
            float2 g0 = *(const float2*)(gate + o0);
            float2 g1 = *(const float2*)(gate + o1);
            splitw(O[u][0] * i0 * g0.x, outh + o0,     outl + o0);
            splitw(O[u][1] * i0 * g0.y, outh + o0 + 1, outl + o0 + 1);
            splitw(O[u][2] * i1 * g1.x, outh + o1,     outl + o1);
            splitw(O[u][3] * i1 * g1.y, outh + o1 + 1, outl + o1 + 1);
        }
    }
}

// ---------------------------------------------------------------------------
// Host launcher
// ---------------------------------------------------------------------------
#define SMEM_ATTN (3 * ABUF)
#define ATTN_GRID 148

extern "C" void kernel_launch(void* const* d_in, const int* in_sizes, int n_in,
                              void* d_out, int out_size) {
    const float* input     = (const float*)d_in[0];
    const float* xl_k_hat  = (const float*)d_in[2];
    const float* xl_v      = (const float*)d_in[3];
    const float* agg_upper = (const float*)d_in[4];
    const float* agg_lower = (const float*)d_in[5];
    const float* W_q       = (const float*)d_in[6];
    const float* W_kvg     = (const float*)d_in[7];
    const float* W_res     = (const float*)d_in[8];
    const float* x_u       = (const float*)d_in[9];
    const float* x_v       = (const float*)d_in[10];
    const float* xl_r      = (const float*)d_in[11];
    const float* codebook  = (const float*)d_in[12];
    float* out = (float*)d_out;

    float *proj, *vv, *gate, *rbd, *csq;
    unsigned long long* zpk;
    int* ctr;
    bf16 *xt_h, *xt_l, *wall_h, *wall_l, *wrest_h, *wrest_l;
    bf16 *qu_h, *qu_l, *qv_h, *qv_l, *kl_h, *kl_l, *khat_h, *khat_l;
    bf16 *cb_h, *cb_l, *xlr_h, *xlr_l, *vt_h, *vt_l, *wvg_h, *wvg_l;

    cudaGetSymbolAddress((void**)&proj, g_proj);
    cudaGetSymbolAddress((void**)&vv, g_vv);
    cudaGetSymbolAddress((void**)&gate, g_gate);
    cudaGetSymbolAddress((void**)&rbd, g_rbd);
    cudaGetSymbolAddress((void**)&csq, g_csq);
    cudaGetSymbolAddress((void**)&zpk, g_zpk);
    cudaGetSymbolAddress((void**)&ctr, g_unit_ctr);
    cudaGetSymbolAddress((void**)&xt_h, g_xt_h);   cudaGetSymbolAddress((void**)&xt_l, g_xt_l);
    cudaGetSymbolAddress((void**)&wall_h, g_wall_h); cudaGetSymbolAddress((void**)&wall_l, g_wall_l);
    cudaGetSymbolAddress((void**)&wrest_h, g_wrest_h); cudaGetSymbolAddress((void**)&wrest_l, g_wrest_l);
    cudaGetSymbolAddress((void**)&qu_h, g_qu_h);   cudaGetSymbolAddress((void**)&qu_l, g_qu_l);
    cudaGetSymbolAddress((void**)&qv_h, g_qv_h);   cudaGetSymbolAddress((void**)&qv_l, g_qv_l);
    cudaGetSymbolAddress((void**)&kl_h, g_kl_h);   cudaGetSymbolAddress((void**)&kl_l, g_kl_l);
    cudaGetSymbolAddress((void**)&khat_h, g_khat_h); cudaGetSymbolAddress((void**)&khat_l, g_khat_l);
    cudaGetSymbolAddress((void**)&cb_h, g_cb_h);   cudaGetSymbolAddress((void**)&cb_l, g_cb_l);
    cudaGetSymbolAddress((void**)&xlr_h, g_xlr_h); cudaGetSymbolAddress((void**)&xlr_l, g_xlr_l);
    cudaGetSymbolAddress((void**)&vt_h, g_vt_h);   cudaGetSymbolAddress((void**)&vt_l, g_vt_l);
    cudaGetSymbolAddress((void**)&wvg_h, g_wvg_h); cudaGetSymbolAddress((void**)&wvg_l, g_wvg_l);

    cudaFuncSetAttribute(attn_kernel, cudaFuncAttributeMaxDynamicSharedMemorySize, SMEM_ATTN);

    // 0. fused preprocessing
    prep_kernel<<<PREP_GRID, 256>>>(W_q, W_kvg, W_res, xl_k_hat, codebook, xl_r, input,
                                    wall_h, wall_l, wrest_h, wrest_l,
                                    khat_h, khat_l, cb_h, cb_l, xlr_h, xlr_l,
                                    xt_h, xt_l, csq, zpk, ctr);

    // 1. fused projection GEMM (Wq | Wkvg), N=4096
    mma_gemm4_kernel<<<dim3(32, 32, 1), 256>>>(xt_h, xt_l, wall_h, wall_l,
                                               proj, 4096, 1024, 1024);

    // 2. per-head LN, biases, silu
    transform_kernel<<<NROWS * CH / 8, 256>>>(proj, x_u, x_v,
                                              qu_h, qu_l, qv_h, qv_l, kl_h, kl_l, vv, gate);

    // 3. merged mid stage: VQ + BD + V gather-transpose
    mid_kernel<<<MID_END, 256>>>(kl_h, kl_l, qv_h, qv_l, cb_h, cb_l, xlr_h, xlr_l,
                                 csq, zpk, rbd, xl_v, vv, agg_upper, vt_h, vt_l);

    // 4. fused attention (persistent work-stealing)
    attn_kernel<<<ATTN_GRID, 256, SMEM_ATTN>>>(qu_h, qu_l, khat_h, khat_l,
                                               cb_h, cb_l, vt_h, vt_l, zpk,
                                               rbd, agg_lower, gate, ctr, wvg_h, wvg_l);

    // 5. output projection
    mma_gemm4_kernel<<<dim3(8, 32, 1), 256>>>(wvg_h, wvg_l, wrest_h, wrest_l,
                                              out, 1024, 1024, 1024);
}

// round 12
// speedup vs baseline: 1.0739x; 1.0739x over previous
#include <cuda_runtime.h>
#include <cuda_bf16.h>
#include <cstdint>

// ---------------------------------------------------------------------------
// Problem constants
// ---------------------------------------------------------------------------
#define CB   8
#define CL   512
#define CM   512
#define CH   8
#define CDK  128
#define CDV  128
#define CS   512
#define CDM  1024
#define CW   1024   // W_REC
#define NBH  64
#define NROWS 4096
#define SCW  1536   // W + S

static __device__ __constant__ const float TAUI = 0.08838834764831845f; // 1/sqrt(128)

typedef __nv_bfloat16 bf16;

// ---------------------------------------------------------------------------
// Scratch
// ---------------------------------------------------------------------------
__device__ float g_proj  [(size_t)NROWS * 4096];   // qraw | k | v | g
__device__ float g_vv    [(size_t)NBH * CL * CDV];
__device__ float g_gate  [(size_t)NROWS * CDM];
__device__ float g_rbd   [(size_t)NBH * CL * CW];
__device__ unsigned long long g_zpk[NBH * CL];
__device__ float g_csq   [CH * CS];
__device__ int   g_unit_ctr;

__device__ bf16 g_xt_h   [(size_t)NROWS * CDM];
__device__ bf16 g_xt_l   [(size_t)NROWS * CDM];
__device__ bf16 g_wall_h [(size_t)4096 * 1024];   // Wq^T | Wkvg^T
__device__ bf16 g_wall_l [(size_t)4096 * 1024];
__device__ bf16 g_wrest_h[(size_t)1024 * 1024];
__device__ bf16 g_wrest_l[(size_t)1024 * 1024];
__device__ bf16 g_qu_h   [(size_t)NBH * CL * CDK];
__device__ bf16 g_qu_l   [(size_t)NBH * CL * CDK];
__device__ bf16 g_qv_h   [(size_t)NBH * CL * CDK];
__device__ bf16 g_qv_l   [(size_t)NBH * CL * CDK];
__device__ bf16 g_kl_h   [(size_t)NBH * CL * CDK];
__device__ bf16 g_kl_l   [(size_t)NBH * CL * CDK];
__device__ bf16 g_khat_h [(size_t)NBH * CM * CDK];
__device__ bf16 g_khat_l [(size_t)NBH * CM * CDK];
__device__ bf16 g_cb_h   [(size_t)CH * CS * CDK];
__device__ bf16 g_cb_l   [(size_t)CH * CS * CDK];
__device__ bf16 g_xlr_h  [(size_t)CH * CW * CDK];
__device__ bf16 g_xlr_l  [(size_t)CH * CW * CDK];
__device__ bf16 g_vt_h   [(size_t)NBH * CDV * SCW];
__device__ bf16 g_vt_l   [(size_t)NBH * CDV * SCW];
__device__ bf16 g_wvg_h  [(size_t)NROWS * CDM];
__device__ bf16 g_wvg_l  [(size_t)NROWS * CDM];

// ---------------------------------------------------------------------------
// primitives
// ---------------------------------------------------------------------------
__device__ __forceinline__ uint32_t cvta_s(const void* p) {
    return (uint32_t)__cvta_generic_to_shared(p);
}
__device__ __forceinline__ void ldmx4(uint32_t addr, uint32_t& r0, uint32_t& r1,
                                      uint32_t& r2, uint32_t& r3) {
    asm volatile("ldmatrix.sync.aligned.m8n8.x4.shared.b16 {%0,%1,%2,%3}, [%4];"
                 : "=r"(r0), "=r"(r1), "=r"(r2), "=r"(r3) : "r"(addr));
}
__device__ __forceinline__ void mma16816(float c[4], const uint32_t a[4], const uint32_t b[2]) {
    asm volatile(
        "mma.sync.aligned.m16n8k16.row.col.f32.bf16.bf16.f32 "
        "{%0,%1,%2,%3}, {%4,%5,%6,%7}, {%8,%9}, {%0,%1,%2,%3};"
        : "+f"(c[0]), "+f"(c[1]), "+f"(c[2]), "+f"(c[3])
        : "r"(a[0]), "r"(a[1]), "r"(a[2]), "r"(a[3]), "r"(b[0]), "r"(b[1]));
}
__device__ __forceinline__ void cpa16(uint32_t d, const void* s) {
    asm volatile("cp.async.ca.shared.global [%0], [%1], 16;" :: "r"(d), "l"(s));
}
__device__ __forceinline__ void cpa_commit() {
    asm volatile("cp.async.commit_group;");
}
template <int NN>
__device__ __forceinline__ void cpa_wait() {
    asm volatile("cp.async.wait_group %0;" :: "n"(NN));
}

__device__ __forceinline__ void splitw(float x, bf16* h, bf16* l) {
    bf16 hh = __float2bfloat16_rn(x);
    *h = hh;
    *l = __float2bfloat16_rn(x - __bfloat162float(hh));
}
__device__ __forceinline__ void split4(float4 v, bf16* hp, bf16* lp) {
    __nv_bfloat162 h0 = __floats2bfloat162_rn(v.x, v.y);
    __nv_bfloat162 h1 = __floats2bfloat162_rn(v.z, v.w);
    float2 f0 = __bfloat1622float2(h0);
    float2 f1 = __bfloat1622float2(h1);
    __nv_bfloat162 l0 = __floats2bfloat162_rn(v.x - f0.x, v.y - f0.y);
    __nv_bfloat162 l1 = __floats2bfloat162_rn(v.z - f1.x, v.w - f1.y);
    uint2 hv, lv;
    hv.x = *(uint32_t*)&h0; hv.y = *(uint32_t*)&h1;
    lv.x = *(uint32_t*)&l0; lv.y = *(uint32_t*)&l1;
    *(uint2*)hp = hv;
    *(uint2*)lp = lv;
}
__device__ __forceinline__ uint32_t packbf(float x, float y) {
    __nv_bfloat162 t = __floats2bfloat162_rn(x, y);
    return *(uint32_t*)&t;
}
__device__ __forceinline__ uint32_t packbf_res(float x, float y, uint32_t hp) {
    __nv_bfloat162 hv = *(__nv_bfloat162*)&hp;
    float2 f = __bfloat1622float2(hv);
    return packbf(x - f.x, y - f.y);
}

// ---------------------------------------------------------------------------
// reductions
// ---------------------------------------------------------------------------
__device__ __forceinline__ float block_sum(float v) {
    __shared__ float sb_[8];
    int tid = threadIdx.x;
    int nw  = blockDim.x >> 5;
    #pragma unroll
    for (int o = 16; o; o >>= 1) v += __shfl_down_sync(0xffffffffu, v, o);
    __syncthreads();
    if ((tid & 31) == 0) sb_[tid >> 5] = v;
    __syncthreads();
    float r = 0.f;
    for (int i = 0; i < nw; ++i) r += sb_[i];
    return r;
}
__device__ __forceinline__ float warp_sum(float v) {
    #pragma unroll
    for (int o = 16; o; o >>= 1) v += __shfl_xor_sync(0xffffffffu, v, o);
    return v;
}

// ---------------------------------------------------------------------------
// Fused preprocessing (one launch, all light blocks)
// ---------------------------------------------------------------------------
#define PS0 1024
#define PS1 (PS0 + 3072)
#define PS2 (PS1 + 1024)
#define PS3 (PS2 + 4096)
#define PS4 (PS3 + 512)
#define PS5 (PS4 + 1024)
#define PS6 (PS5 + 4096)
#define PS7 (PS6 + 512)
#define PS8 (PS7 + 32)
#define PREP_GRID PS8

__device__ __forceinline__ void do_transpose(const float* __restrict__ src,
                                             bf16* __restrict__ dh,
                                             bf16* __restrict__ dl,
                                             int R, int C, int id,
                                             float (*tile)[33]) {
    int bx = id % (C >> 5), by = id / (C >> 5);
    int c0 = bx * 32, r0 = by * 32;
    int x = threadIdx.x & 31, y = (threadIdx.x >> 5) * 4;
    #pragma unroll
    for (int i = 0; i < 4; ++i)
        tile[y + i][x] = src[(size_t)(r0 + y + i) * C + c0 + x];
    __syncthreads();
    #pragma unroll
    for (int i = 0; i < 4; ++i) {
        size_t o = (size_t)(c0 + y + i) * R + r0 + x;
        splitw(tile[x][y + i], dh + o, dl + o);
    }
}
__device__ __forceinline__ void do_convert(const float* __restrict__ src,
                                           bf16* __restrict__ h,
                                           bf16* __restrict__ l, int id) {
    size_t idx = (size_t)id * 256 + threadIdx.x;
    float4 v = ((const float4*)src)[idx];
    split4(v, h + idx * 4, l + idx * 4);
}

__global__ void __launch_bounds__(256) prep_kernel(
    const float* __restrict__ W_q, const float* __restrict__ W_kvg,
    const float* __restrict__ W_res,
    const float* __restrict__ xl_k_hat, const float* __restrict__ codebook,
    const float* __restrict__ xl_r, const float* __restrict__ input,
    bf16* wall_h, bf16* wall_l, bf16* wrest_h, bf16* wrest_l,
    bf16* khat_h, bf16* khat_l, bf16* cb_h, bf16* cb_l,
    bf16* xlr_h, bf16* xlr_l, bf16* xt_h, bf16* xt_l,
    float* csq, unsigned long long* zpk, int* ctr) {

    __shared__ float tile[32][33];
    int bid = blockIdx.x;
    int tid = threadIdx.x;

    if (bid < PS0) {
        do_transpose(W_q, wall_h, wall_l, 1024, 1024, bid, tile);
    } else if (bid < PS1) {
        do_transpose(W_kvg, wall_h + (size_t)1024 * 1024, wall_l + (size_t)1024 * 1024,
                     1024, 3072, bid - PS0, tile);
    } else if (bid < PS2) {
        do_transpose(W_res, wrest_h, wrest_l, 1024, 1024, bid - PS1, tile);
    } else if (bid < PS3) {
        do_convert(xl_k_hat, khat_h, khat_l, bid - PS2);
    } else if (bid < PS4) {
        do_convert(codebook, cb_h, cb_l, bid - PS3);
    } else if (bid < PS5) {
        do_convert(xl_r, xlr_h, xlr_l, bid - PS4);
    } else if (bid < PS6) {
        int row = bid - PS5;
        const float* xr = input + (size_t)row * CDM;
        float4 v = *(const float4*)(xr + tid * 4);
        float s = v.x + v.y + v.z + v.w;
        float mu = block_sum(s) * (1.f / 1024.f);
        v.x -= mu; v.y -= mu; v.z -= mu; v.w -= mu;
        float s2 = v.x * v.x + v.y * v.y + v.z * v.z + v.w * v.w;
        float rstd = rsqrtf(block_sum(s2) * (1.f / 1024.f) + 1e-6f);
        v.x *= rstd; v.y *= rstd; v.z *= rstd; v.w *= rstd;
        split4(v, xt_h + (size_t)row * CDM + tid * 4, xt_l + (size_t)row * CDM + tid * 4);
    } else if (bid < PS7) {
        int wid  = tid >> 5, lane = tid & 31;
        int row = (bid - PS6) * 8 + wid;
        float4 v = *(const float4*)(codebook + (size_t)row * CDK + lane * 4);
        float s = warp_sum(v.x * v.x + v.y * v.y + v.z * v.z + v.w * v.w);
        if (lane == 0) csq[row] = s;
    } else {
        int id = bid - PS7;
        size_t base = (size_t)id * 1024 + tid * 4;
        zpk[base + 0] = ~0ull; zpk[base + 1] = ~0ull;
        zpk[base + 2] = ~0ull; zpk[base + 3] = ~0ull;
        if (id == 0 && tid == 0) *ctr = 0;
    }
}

// ---------------------------------------------------------------------------
// Vt gather-transpose (lean, high-occupancy — NOT merged with GEMMs)
// ---------------------------------------------------------------------------
__global__ void __launch_bounds__(256) vt_kernel(const float* __restrict__ xl_v,
                                                 const float* __restrict__ vv,
                                                 const float* __restrict__ aggu,
                                                 bf16* __restrict__ vth,
                                                 bf16* __restrict__ vtl) {
    __shared__ float tile[32][33];
    int zb = blockIdx.z;
    int w0 = blockIdx.x * 32, v0 = blockIdx.y * 32;
    int x = threadIdx.x & 31, y = (threadIdx.x >> 5) * 4;
    #pragma unroll
    for (int i = 0; i < 4; ++i) {
        int w = w0 + y + i;
        const float* srcrow;
        if (w < CM)      srcrow = xl_v + ((size_t)zb * CM + w) * CDV;
        else if (w < CW) srcrow = vv   + ((size_t)zb * CL + (w - CM)) * CDV;
        else             srcrow = aggu + ((size_t)zb * CS + (w - CW)) * CDV;
        tile[y + i][x] = srcrow[v0 + x];
    }
    __syncthreads();
    #pragma unroll
    for (int i = 0; i < 4; ++i) {
        size_t o = ((size_t)zb * CDV + v0 + y + i) * SCW + w0 + x;
        splitw(tile[x][y + i], vth + o, vtl + o);
    }
}

// ---------------------------------------------------------------------------
// per-(b,l,h) transform (reads fused proj buffer)
// ---------------------------------------------------------------------------
__global__ void __launch_bounds__(256) transform_kernel(const float* __restrict__ proj,
                                                        const float* __restrict__ x_u,
                                                        const float* __restrict__ x_v,
                                                        bf16* __restrict__ quh, bf16* __restrict__ qul,
                                                        bf16* __restrict__ qvh, bf16* __restrict__ qvl,
                                                        bf16* __restrict__ klh, bf16* __restrict__ kll,
                                                        float* __restrict__ vv,
                                                        float* __restrict__ gate) {
    int wid  = threadIdx.x >> 5;
    int lane = threadIdx.x & 31;
    int idx = blockIdx.x * 8 + wid;
    int h  = idx & 7;
    int bl = idx >> 3;
    int b = bl >> 9, l = bl & 511;
    int d0 = lane * 4;
    const float* prow = proj + (size_t)bl * 4096 + h * CDK + d0;

    float4 q = *(const float4*)(prow);
    float mu = warp_sum(q.x + q.y + q.z + q.w) * (1.f / 128.f);
    q.x -= mu; q.y -= mu; q.z -= mu; q.w -= mu;
    float var = warp_sum(q.x * q.x + q.y * q.y + q.z * q.z + q.w * q.w) * (1.f / 128.f);
    float rs = rsqrtf(var + 1e-6f);
    float4 xu = *(const float4*)(x_u + h * CDK + d0);
    float4 xv = *(const float4*)(x_v + h * CDK + d0);
    size_t o = (((size_t)b * CH + h) * CL + l) * CDK + d0;
    split4(make_float4(q.x * rs + xu.x, q.y * rs + xu.y, q.z * rs + xu.z, q.w * rs + xu.w),
           quh + o, qul + o);
    split4(make_float4(q.x * rs + xv.x, q.y * rs + xv.y, q.z * rs + xv.z, q.w * rs + xv.w),
           qvh + o, qvl + o);

    float4 k = *(const float4*)(prow + 1024);
    float kmu = warp_sum(k.x + k.y + k.z + k.w) * (1.f / 128.f);
    k.x -= kmu; k.y -= kmu; k.z -= kmu; k.w -= kmu;
    float kvar = warp_sum(k.x * k.x + k.y * k.y + k.z * k.z + k.w * k.w) * (1.f / 128.f);
    float krs = rsqrtf(kvar + 1e-6f);
    split4(make_float4(k.x * krs, k.y * krs, k.z * krs, k.w * krs), klh + o, kll + o);

    *(float4*)(vv + o) = *(const float4*)(prow + 2048);

    float4 gg = *(const float4*)(prow + 3072);
    float4 gs;
    gs.x = gg.x / (1.f + __expf(-gg.x));
    gs.y = gg.y / (1.f + __expf(-gg.y));
    gs.z = gg.z / (1.f + __expf(-gg.z));
    gs.w = gg.w / (1.f + __expf(-gg.w));
    *(float4*)(gate + (size_t)bl * CDM + h * CDK + d0) = gs;
}

// ---------------------------------------------------------------------------
// NT tensor-core GEMM body (bf16x3, 3-stage cp.async). MODE: 0=BD, 3=VQ, 4=PROJ
// ---------------------------------------------------------------------------
#define STG_B 12288
#define CMP_B 6144
#define SBOFF 36864
template <int MODE>
__device__ __forceinline__ void gemm_body(
    char* smem, int bm, int bn, int bh,
    const bf16* __restrict__ Ah, const bf16* __restrict__ Al,
    const bf16* __restrict__ Bh, const bf16* __restrict__ Bl,
    const float* __restrict__ csq,
    unsigned long long* zpk_out,
    float* __restrict__ outp,
    int N, int K, int lda) {

    int tid  = threadIdx.x;
    int lane = tid & 31, warp = tid >> 5;
    int wm = warp >> 2, wn = warp & 3;
    int h  = bh & 7;

    if (MODE == 0 && (bn + bm) < 257) return;   // BD dead tiles

    size_t aoff = (MODE == 4) ? 0 : (size_t)bh * CL * CDK;

    int srow = tid >> 1;
    int sc8  = (tid & 1) * 8;
    const bf16* a_h = Ah + aoff + (size_t)(bm + srow) * lda + sc8;
    const bf16* a_l = Al + aoff + (size_t)(bm + srow) * lda + sc8;
    const bf16 *b_h, *b_l;
    {
        int n = bn + srow;
        size_t boff;
        if (MODE == 0)      boff = ((size_t)h * CW + n) * CDK;
        else if (MODE == 3) boff = ((size_t)h * CS + n) * CDK;
        else                boff = (size_t)n * K;
        b_h = Bh + boff + sc8; b_l = Bl + boff + sc8;
    }

    uint32_t sA = cvta_s(smem);
    uint32_t sB = sA + SBOFF;
    uint32_t dA = sA + (uint32_t)(srow * 24 + sc8) * 2;
    uint32_t dB = sB + (uint32_t)(srow * 24 + sc8) * 2;

    int a_off = (wm * 64 + (lane & 15)) * 24 + ((lane >> 4) << 3);
    int b_off = (wn * 32 + ((lane >> 4) << 3) + (lane & 7)) * 24 + (((lane >> 3) & 1) << 3);

    float acc[4][4][4] = {};
    int T = K >> 4;

    cpa16(dA,         a_h);  cpa16(dA + CMP_B, a_l);
    cpa16(dB,         b_h);  cpa16(dB + CMP_B, b_l);
    cpa_commit();

    #pragma unroll 1
    for (int kt = 0; kt < T; ++kt) {
        if (kt + 1 < T) {
            int st = (kt + 1) % 3;
            int k0 = (kt + 1) * 16;
            cpa16(dA + st * STG_B,         a_h + k0);
            cpa16(dA + st * STG_B + CMP_B, a_l + k0);
            cpa16(dB + st * STG_B,         b_h + k0);
            cpa16(dB + st * STG_B + CMP_B, b_l + k0);
            cpa_commit();
            cpa_wait<1>();
        } else {
            cpa_wait<0>();
        }
        __syncthreads();

        int cs = kt % 3;
        uint32_t aH = sA + cs * STG_B + (uint32_t)a_off * 2;
        uint32_t bH = sB + cs * STG_B + (uint32_t)b_off * 2;
        uint32_t ah[4][4], al[4][4], bhf[4][2], blf[4][2];
        #pragma unroll
        for (int t = 0; t < 4; ++t) {
            ldmx4(aH + t * 768,         ah[t][0], ah[t][1], ah[t][2], ah[t][3]);
            ldmx4(aH + CMP_B + t * 768, al[t][0], al[t][1], al[t][2], al[t][3]);
        }
        #pragma unroll
        for (int u2 = 0; u2 < 2; ++u2) {
            uint32_t r0, r1, r2, r3;
            ldmx4(bH + u2 * 768, r0, r1, r2, r3);
            bhf[2 * u2][0] = r0; bhf[2 * u2][1] = r1;
            bhf[2 * u2 + 1][0] = r2; bhf[2 * u2 + 1][1] = r3;
            ldmx4(bH + CMP_B + u2 * 768, r0, r1, r2, r3);
            blf[2 * u2][0] = r0; blf[2 * u2][1] = r1;
            blf[2 * u2 + 1][0] = r2; blf[2 * u2 + 1][1] = r3;
        }
        #pragma unroll
        for (int t = 0; t < 4; ++t)
            #pragma unroll
            for (int u = 0; u < 4; ++u) {
                mma16816(acc[t][u], ah[t], bhf[u]);
                mma16816(acc[t][u], ah[t], blf[u]);
                mma16816(acc[t][u], al[t], bhf[u]);
            }
    }

    int g  = lane >> 2;
    int qd = lane & 3;

    if constexpr (MODE == 4) {
        #pragma unroll
        for (int t = 0; t < 4; ++t) {
            int r = bm + wm * 64 + t * 16 + g;
            #pragma unroll
            for (int u = 0; u < 4; ++u) {
                int c = bn + wn * 32 + u * 8 + qd * 2;
                *(float2*)(outp + (size_t)r * N + c) =
                    make_float2(acc[t][u][0], acc[t][u][1]);
                *(float2*)(outp + (size_t)(r + 8) * N + c) =
                    make_float2(acc[t][u][2], acc[t][u][3]);
            }
        }
    } else if constexpr (MODE == 0) {
        #pragma unroll
        for (int t = 0; t < 4; ++t) {
            int l = bm + wm * 64 + t * 16 + g;
            #pragma unroll
            for (int u = 0; u < 4; ++u) {
                int c = bn + wn * 32 + u * 8 + qd * 2;
                *(float2*)(outp + ((size_t)bh * CL + l) * CW + c) =
                    make_float2(acc[t][u][0] * TAUI, acc[t][u][1] * TAUI);
                *(float2*)(outp + ((size_t)bh * CL + l + 8) * CW + c) =
                    make_float2(acc[t][u][2] * TAUI, acc[t][u][3] * TAUI);
            }
        }
    } else {   // VQ argmin
        unsigned long long* zmin = reinterpret_cast<unsigned long long*>(smem);
        __syncthreads();
        if (tid < 128) zmin[tid] = ~0ull;
        __syncthreads();
        #pragma unroll
        for (int t = 0; t < 4; ++t) {
            unsigned long long b0 = ~0ull, b1 = ~0ull;
            #pragma unroll
            for (int u = 0; u < 4; ++u) {
                #pragma unroll
                for (int p = 0; p < 2; ++p) {
                    int s = bn + wn * 32 + u * 8 + qd * 2 + p;
                    float cs = csq[h * CS + s];
                    {
                        float val = cs - 2.f * acc[t][u][p];
                        unsigned uu = __float_as_uint(val);
                        uu = (uu & 0x80000000u) ? ~uu : (uu | 0x80000000u);
                        unsigned long long key = ((unsigned long long)uu << 32) | (unsigned)s;
                        if (key < b0) b0 = key;
                    }
                    {
                        float val = cs - 2.f * acc[t][u][2 + p];
                        unsigned uu = __float_as_uint(val);
                        uu = (uu & 0x80000000u) ? ~uu : (uu | 0x80000000u);
                        unsigned long long key = ((unsigned long long)uu << 32) | (unsigned)s;
                        if (key < b1) b1 = key;
                    }
                }
            }
            unsigned long long o;
            o = __shfl_xor_sync(0xffffffffu, b0, 1); if (o < b0) b0 = o;
            o = __shfl_xor_sync(0xffffffffu, b0, 2); if (o < b0) b0 = o;
            o = __shfl_xor_sync(0xffffffffu, b1, 1); if (o < b1) b1 = o;
            o = __shfl_xor_sync(0xffffffffu, b1, 2); if (o < b1) b1 = o;
            if (qd == 0) {
                atomicMin(&zmin[wm * 64 + t * 16 + g], b0);
                atomicMin(&zmin[wm * 64 + t * 16 + g + 8], b1);
            }
        }
        __syncthreads();
        if (tid < 128)
            atomicMin(&zpk_out[(size_t)bh * CL + bm + tid], zmin[tid]);
    }
}

// wrapper kernels (homogeneous footprints)
__global__ void __launch_bounds__(256) mma_gemm4_kernel(
    const bf16* __restrict__ Ah, const bf16* __restrict__ Al,
    const bf16* __restrict__ Bh, const bf16* __restrict__ Bl,
    float* __restrict__ outp, int N, int K, int lda) {
    __shared__ __align__(16) char smem[73728];
    gemm_body<4>(smem, blockIdx.y * 128, blockIdx.x * 128, 0,
                 Ah, Al, Bh, Bl, nullptr, nullptr, outp, N, K, lda);
}
__global__ void __launch_bounds__(256) vq_gemm_kernel(
    const bf16* __restrict__ Ah, const bf16* __restrict__ Al,
    const bf16* __restrict__ Bh, const bf16* __restrict__ Bl,
    const float* __restrict__ csq, unsigned long long* zpk) {
    __shared__ __align__(16) char smem[73728];
    gemm_body<3>(smem, blockIdx.y * 128, blockIdx.x * 128, blockIdx.z,
                 Ah, Al, Bh, Bl, csq, zpk, nullptr, 512, 128, 128);
}
__global__ void __launch_bounds__(256) bd_gemm_kernel(
    const bf16* __restrict__ Ah, const bf16* __restrict__ Al,
    const bf16* __restrict__ Bh, const bf16* __restrict__ Bl,
    float* __restrict__ rbd) {
    __shared__ __align__(16) char smem[73728];
    gemm_body<0>(smem, blockIdx.y * 128, blockIdx.x * 128, blockIdx.z,
                 Ah, Al, Bh, Bl, nullptr, nullptr, rbd, 1024, 128, 128);
}

// ---------------------------------------------------------------------------
// Fused attention (persistent, work-stealing)
// ---------------------------------------------------------------------------
#define APITCH 272
#define APLANE 34816
#define ABUF   69632
#define NUNITS 256
__global__ void __launch_bounds__(256) attn_kernel(
    const bf16* __restrict__ quh, const bf16* __restrict__ qul,
    const bf16* __restrict__ khat_h, const bf16* __restrict__ khat_l,
    const bf16* __restrict__ cb_h, const bf16* __restrict__ cb_l,
    const bf16* __restrict__ vt_h, const bf16* __restrict__ vt_l,
    const unsigned long long* __restrict__ zpk,
    const float* __restrict__ rbd,
    const float* __restrict__ agg_lower,
    const float* __restrict__ gate,
    int* __restrict__ unit_ctr,
    bf16* __restrict__ outh, bf16* __restrict__ outl) {

    extern __shared__ __align__(16) char smem_raw[];
    uint32_t sQU = cvta_s(smem_raw);
    uint32_t sKT = sQU + ABUF;
    uint32_t sVT = sQU + 2 * ABUF;
    __shared__ int s_unit;

    int tid  = threadIdx.x;
    int lane = tid & 31, warp = tid >> 5;
    int g = lane >> 2, qd = lane & 3;

    for (;;) {
        __syncthreads();
        if (tid == 0) s_unit = atomicAdd(unit_ctr, 1);
        __syncthreads();
        int unit = s_unit;
        if (unit >= NUNITS) break;

        int bm = (unit >> 6) * 128;
        int bh = unit & 63;
        int h  = bh & 7;
        int b  = bh >> 3;

        int tiles[12]; int nt = 0;
        #pragma unroll
        for (int j = 0; j < 12; ++j)
            if (!(j < 8 && j * 128 >= bm + CM + 128)) tiles[nt++] = j;

        auto load_qu = [&]() {
            size_t qoff = (size_t)bh * CL * CDK;
            #pragma unroll
            for (int i = 0; i < 8; ++i) {
                int id = tid + i * 256;
                int r = id >> 4, c = id & 15;
                uint32_t d = sQU + r * APITCH + c * 16;
                cpa16(d,          quh + qoff + (size_t)(bm + r) * CDK + c * 8);
                cpa16(d + APLANE, qul + qoff + (size_t)(bm + r) * CDK + c * 8);
            }
        };
        auto load_kt = [&](int j) {
            #pragma unroll
            for (int i = 0; i < 8; ++i) {
                int id = tid + i * 256;
                int r = id >> 4, c = id & 15;
                int n = j * 128 + r;
                const bf16 *sh, *sl;
                if (j < 4) {
                    size_t o = ((size_t)bh * CM + n) * CDK;
                    sh = khat_h + o; sl = khat_l + o;
                } else if (j < 8) {
                    unsigned zi = (unsigned)(zpk[(size_t)bh * CL + (n - CM)] & 0xffffffffull);
                    size_t o = ((size_t)h * CS + zi) * CDK;
                    sh = cb_h + o; sl = cb_l + o;
                } else {
                    size_t o = ((size_t)h * CS + (n - CW)) * CDK;
                    sh = cb_h + o; sl = cb_l + o;
                }
                uint32_t d = sKT + r * APITCH + c * 16;
                cpa16(d,          sh + c * 8);
                cpa16(d + APLANE, sl + c * 8);
            }
        };
        auto load_vt = [&](int j) {
            #pragma unroll
            for (int i = 0; i < 8; ++i) {
                int id = tid + i * 256;
                int r = id >> 4, c = id & 15;
                size_t o = ((size_t)bh * CDV + r) * SCW + j * 128 + c * 8;
                uint32_t d = sVT + r * APITCH + c * 16;
                cpa16(d,          vt_h + o);
                cpa16(d + APLANE, vt_l + o);
            }
        };

        uint32_t quB = sQU + (uint32_t)(warp * 16 + (lane & 15)) * APITCH + ((lane >> 4) << 4);
        uint32_t bB  = (uint32_t)((((lane >> 4) << 3) + (lane & 7)) * APITCH) + (((lane >> 3) & 1) << 4);

        int l0 = bm + warp * 16 + g;
        int l1 = l0 + 8;

        float O[16][4] = {};
        float m0 = -3.4e38f, m1 = -3.4e38f, d0 = 0.f, d1 = 0.f;

        load_qu();
        load_kt(tiles[0]);
        cpa_commit();

        #pragma unroll 1
        for (int ti = 0; ti < nt; ++ti) {
            int j = tiles[ti];
            cpa_wait<0>();
            __syncthreads();
            load_vt(j);
            cpa_commit();

            float S[16][4] = {};
            #pragma unroll
            for (int kg = 0; kg < 8; ++kg) {
                uint32_t ah[4], al[4];
                ldmx4(quB + kg * 32,          ah[0], ah[1], ah[2], ah[3]);
                ldmx4(quB + APLANE + kg * 32, al[0], al[1], al[2], al[3]);
                #pragma unroll
                for (int nf = 0; nf < 8; ++nf) {
                    uint32_t base = sKT + bB + nf * (16 * APITCH) + kg * 32;
                    uint32_t p0, p1, p2, p3, q0, q1, q2, q3;
                    ldmx4(base,          p0, p1, p2, p3);
                    ldmx4(base + APLANE, q0, q1, q2, q3);
                    uint32_t bp[2], bq[2];
                    bp[0] = p0; bp[1] = p1; bq[0] = q0; bq[1] = q1;
                    mma16816(S[nf * 2], ah, bp);
                    mma16816(S[nf * 2], ah, bq);
                    mma16816(S[nf * 2], al, bp);
                    bp[0] = p2; bp[1] = p3; bq[0] = q2; bq[1] = q3;
                    mma16816(S[nf * 2 + 1], ah, bp);
                    mma16816(S[nf * 2 + 1], ah, bq);
                    mma16816(S[nf * 2 + 1], al, bp);
                }
            }

            if (j < 8) {
                const float* rr0 = rbd + ((size_t)bh * CL + l0) * CW + (CL - 1) - l0;
                const float* rr1 = rbd + ((size_t)bh * CL + l1) * CW + (CL - 1) - l1;
                int wb = j * 128 + qd * 2;
                #pragma unroll
                for (int u = 0; u < 16; ++u) {
                    int w = wb + u * 8;
                    S[u][0] = (w     <= l0 + CM) ? S[u][0] * TAUI + rr0[w]     : -1e30f;
                    S[u][1] = (w + 1 <= l0 + CM) ? S[u][1] * TAUI + rr0[w + 1] : -1e30f;
                    S[u][2] = (w     <= l1 + CM) ? S[u][2] * TAUI + rr1[w]     : -1e30f;
                    S[u][3] = (w + 1 <= l1 + CM) ? S[u][3] * TAUI + rr1[w + 1] : -1e30f;
                }
            } else {
                int sb = (j - 8) * 128 + qd * 2;
                #pragma unroll
                for (int u = 0; u < 16; ++u) {
                    int s = sb + u * 8;
                    float a0 = agg_lower[(size_t)bh * CS + s];
                    float a1 = agg_lower[(size_t)bh * CS + s + 1];
                    float b0 = (a0 > 0.f) ? logf(fmaxf(a0, 1e-30f)) : -1e30f;
                    float b1 = (a1 > 0.f) ? logf(fmaxf(a1, 1e-30f)) : -1e30f;
                    S[u][0] = S[u][0] * TAUI + b0;
                    S[u][1] = S[u][1] * TAUI + b1;
                    S[u][2] = S[u][2] * TAUI + b0;
                    S[u][3] = S[u][3] * TAUI + b1;
                }
            }

            float mx0 = -3.4e38f, mx1 = -3.4e38f;
            #pragma unroll
            for (int u = 0; u < 16; ++u) {
                mx0 = fmaxf(mx0, fmaxf(S[u][0], S[u][1]));
                mx1 = fmaxf(mx1, fmaxf(S[u][2], S[u][3]));
            }
            mx0 = fmaxf(mx0, __shfl_xor_sync(0xffffffffu, mx0, 1));
            mx0 = fmaxf(mx0, __shfl_xor_sync(0xffffffffu, mx0, 2));
            mx1 = fmaxf(mx1, __shfl_xor_sync(0xffffffffu, mx1, 1));
            mx1 = fmaxf(mx1, __shfl_xor_sync(0xffffffffu, mx1, 2));
            float nm0 = fmaxf(m0, mx0), nm1 = fmaxf(m1, mx1);
            float al0 = __expf(m0 - nm0), al1 = __expf(m1 - nm1);
            m0 = nm0; m1 = nm1;
            float s0 = 0.f, s1 = 0.f;
            #pragma unroll
            for (int u = 0; u < 16; ++u) {
                S[u][0] = __expf(S[u][0] - m0);
                S[u][1] = __expf(S[u][1] - m0);
                S[u][2] = __expf(S[u][2] - m1);
                S[u][3] = __expf(S[u][3] - m1);
                s0 += S[u][0] + S[u][1];
                s1 += S[u][2] + S[u][3];
            }
            s0 += __shfl_xor_sync(0xffffffffu, s0, 1);
            s0 += __shfl_xor_sync(0xffffffffu, s0, 2);
            s1 += __shfl_xor_sync(0xffffffffu, s1, 1);
            s1 += __shfl_xor_sync(0xffffffffu, s1, 2);
            d0 = d0 * al0 + s0;
            d1 = d1 * al1 + s1;
            #pragma unroll
            for (int u = 0; u < 16; ++u) {
                O[u][0] *= al0; O[u][1] *= al0;
                O[u][2] *= al1; O[u][3] *= al1;
            }

            cpa_wait<0>();
            __syncthreads();
            if (ti + 1 < nt) { load_kt(tiles[ti + 1]); cpa_commit(); }

            #pragma unroll
            for (int kg = 0; kg < 8; ++kg) {
                int u2 = kg * 2;
                uint32_t pah[4], pal[4];
                pah[0] = packbf(S[u2][0], S[u2][1]);
                pah[1] = packbf(S[u2][2], S[u2][3]);
                pah[2] = packbf(S[u2 + 1][0], S[u2 + 1][1]);
                pah[3] = packbf(S[u2 + 1][2], S[u2 + 1][3]);
                pal[0] = packbf_res(S[u2][0], S[u2][1], pah[0]);
                pal[1] = packbf_res(S[u2][2], S[u2][3], pah[1]);
                pal[2] = packbf_res(S[u2 + 1][0], S[u2 + 1][1], pah[2]);
                pal[3] = packbf_res(S[u2 + 1][2], S[u2 + 1][3], pah[3]);
                #pragma unroll
                for (int nf = 0; nf < 8; ++nf) {
                    uint32_t base = sVT + bB + nf * (16 * APITCH) + kg * 32;
                    uint32_t p0, p1, p2, p3, q0, q1, q2, q3;
                    ldmx4(base,          p0, p1, p2, p3);
                    ldmx4(base + APLANE, q0, q1, q2, q3);
                    uint32_t bp[2], bq[2];
                    bp[0] = p0; bp[1] = p1; bq[0] = q0; bq[1] = q1;
                    mma16816(O[nf * 2], pah, bp);
                    mma16816(O[nf * 2], pah, bq);
                    mma16816(O[nf * 2], pal, bp);
                    bp[0] = p2; bp[1] = p3; bq[0] = q2; bq[1] = q3;
                    mma16816(O[nf * 2 + 1], pah, bp);
                    mma16816(O[nf * 2 + 1], pah, bq);
                    mma16816(O[nf * 2 + 1], pal, bp);
                }
            }
        }

        float i0 = 1.f / d0, i1 = 1.f / d1;
        #pragma unroll
        for (int u = 0; u < 16; ++u) {
            int c = (u << 3) + qd * 2;
            size_t o0 = ((size_t)b * CL + l0) * CDM + h * CDV + c;
            size_t o1 = ((size_t)b * CL + l1) * CDM + h * CDV + c;
            float2 g0 = *(const float2*)(gate + o0);
            float2 g1 = *(const float2*)(gate + o1);
            splitw(O[u][0] * i0 * g0.x, outh + o0,     outl + o0);
            splitw(O[u][1] * i0 * g0.y, outh + o0 + 1, outl + o0 + 1);
            splitw(O[u][2] * i1 * g1.x, outh + o1,     outl + o1);
            splitw(O[u][3] * i1 * g1.y, outh + o1 + 1, outl + o1 + 1);
        }
    }
}

// ---------------------------------------------------------------------------
// Host launcher
// ---------------------------------------------------------------------------
#define SMEM_ATTN (3 * ABUF)
#define ATTN_GRID 148

extern "C" void kernel_launch(void* const* d_in, const int* in_sizes, int n_in,
                              void* d_out, int out_size) {
    const float* input     = (const float*)d_in[0];
    const float* xl_k_hat  = (const float*)d_in[2];
    const float* xl_v      = (const float*)d_in[3];
    const float* agg_upper = (const float*)d_in[4];
    const float* agg_lower = (const float*)d_in[5];
    const float* W_q       = (const float*)d_in[6];
    const float* W_kvg     = (const float*)d_in[7];
    const float* W_res     = (const float*)d_in[8];
    const float* x_u       = (const float*)d_in[9];
    const float* x_v       = (const float*)d_in[10];
    const float* xl_r      = (const float*)d_in[11];
    const float* codebook  = (const float*)d_in[12];
    float* out = (float*)d_out;

    float *proj, *vv, *gate, *rbd, *csq;
    unsigned long long* zpk;
    int* ctr;
    bf16 *xt_h, *xt_l, *wall_h, *wall_l, *wrest_h, *wrest_l;
    bf16 *qu_h, *qu_l, *qv_h, *qv_l, *kl_h, *kl_l, *khat_h, *khat_l;
    bf16 *cb_h, *cb_l, *xlr_h, *xlr_l, *vt_h, *vt_l, *wvg_h, *wvg_l;

    cudaGetSymbolAddress((void**)&proj, g_proj);
    cudaGetSymbolAddress((void**)&vv, g_vv);
    cudaGetSymbolAddress((void**)&gate, g_gate);
    cudaGetSymbolAddress((void**)&rbd, g_rbd);
    cudaGetSymbolAddress((void**)&csq, g_csq);
    cudaGetSymbolAddress((void**)&zpk, g_zpk);
    cudaGetSymbolAddress((void**)&ctr, g_unit_ctr);
    cudaGetSymbolAddress((void**)&xt_h, g_xt_h);   cudaGetSymbolAddress((void**)&xt_l, g_xt_l);
    cudaGetSymbolAddress((void**)&wall_h, g_wall_h); cudaGetSymbolAddress((void**)&wall_l, g_wall_l);
    cudaGetSymbolAddress((void**)&wrest_h, g_wrest_h); cudaGetSymbolAddress((void**)&wrest_l, g_wrest_l);
    cudaGetSymbolAddress((void**)&qu_h, g_qu_h);   cudaGetSymbolAddress((void**)&qu_l, g_qu_l);
    cudaGetSymbolAddress((void**)&qv_h, g_qv_h);   cudaGetSymbolAddress((void**)&qv_l, g_qv_l);
    cudaGetSymbolAddress((void**)&kl_h, g_kl_h);   cudaGetSymbolAddress((void**)&kl_l, g_kl_l);
    cudaGetSymbolAddress((void**)&khat_h, g_khat_h); cudaGetSymbolAddress((void**)&khat_l, g_khat_l);
    cudaGetSymbolAddress((void**)&cb_h, g_cb_h);   cudaGetSymbolAddress((void**)&cb_l, g_cb_l);
    cudaGetSymbolAddress((void**)&xlr_h, g_xlr_h); cudaGetSymbolAddress((void**)&xlr_l, g_xlr_l);
    cudaGetSymbolAddress((void**)&vt_h, g_vt_h);   cudaGetSymbolAddress((void**)&vt_l, g_vt_l);
    cudaGetSymbolAddress((void**)&wvg_h, g_wvg_h); cudaGetSymbolAddress((void**)&wvg_l, g_wvg_l);

    cudaFuncSetAttribute(attn_kernel, cudaFuncAttributeMaxDynamicSharedMemorySize, SMEM_ATTN);

    // 0. fused preprocessing
    prep_kernel<<<PREP_GRID, 256>>>(W_q, W_kvg, W_res, xl_k_hat, codebook, xl_r, input,
                                    wall_h, wall_l, wrest_h, wrest_l,
                                    khat_h, khat_l, cb_h, cb_l, xlr_h, xlr_l,
                                    xt_h, xt_l, csq, zpk, ctr);

    // 1. fused projection GEMM (Wq | Wkvg), N=4096
    mma_gemm4_kernel<<<dim3(32, 32, 1), 256>>>(xt_h, xt_l, wall_h, wall_l,
                                               proj, 4096, 1024, 1024);

    // 2. per-head LN, biases, silu
    transform_kernel<<<NROWS * CH / 8, 256>>>(proj, x_u, x_v,
                                              qu_h, qu_l, qv_h, qv_l, kl_h, kl_l, vv, gate);

    // 3. V gather-transpose (lean kernel, high occupancy)
    vt_kernel<<<dim3(SCW / 32, CDV / 32, NBH), 256>>>(xl_v, vv, agg_upper, vt_h, vt_l);

    // 4. VQ argmin
    vq_gemm_kernel<<<dim3(4, 4, NBH), 256>>>(kl_h, kl_l, cb_h, cb_l, csq, zpk);

    // 5. BD (dead tiles skipped in-kernel)
    bd_gemm_kernel<<<dim3(8, 4, NBH), 256>>>(qv_h, qv_l, xlr_h, xlr_l, rbd);

    // 6. fused attention (persistent work-stealing)
    attn_kernel<<<ATTN_GRID, 256, SMEM_ATTN>>>(qu_h, qu_l, khat_h, khat_l,
                                               cb_h, cb_l, vt_h, vt_l, zpk,
                                               rbd, agg_lower, gate, ctr, wvg_h, wvg_l);

    // 7. output projection
    mma_gemm4_kernel<<<dim3(8, 32, 1), 256>>>(wvg_h, wvg_l, wrest_h, wrest_l,
                                              out, 1024, 1024, 1024);
}

// round 13
// speedup vs baseline: 1.1041x; 1.0282x over previous
#include <cuda_runtime.h>
#include <cuda_bf16.h>
#include <cstdint>

// ---------------------------------------------------------------------------
// Problem constants
// ---------------------------------------------------------------------------
#define CB   8
#define CL   512
#define CM   512
#define CH   8
#define CDK  128
#define CDV  128
#define CS   512
#define CDM  1024
#define CW   1024   // W_REC
#define NBH  64
#define NROWS 4096
#define SCW  1536   // W + S

static __device__ __constant__ const float TAUI = 0.08838834764831845f; // 1/sqrt(128)

typedef __nv_bfloat16 bf16;

// ---------------------------------------------------------------------------
// Scratch
// ---------------------------------------------------------------------------
__device__ float g_proj  [(size_t)NROWS * 4096];   // qraw | k | v | g
__device__ float g_vv    [(size_t)NBH * CL * CDV];
__device__ float g_gate  [(size_t)NROWS * CDM];
__device__ float g_rbd   [(size_t)NBH * CL * CW];
__device__ unsigned long long g_zpk[NBH * CL];
__device__ float g_csq   [CH * CS];
__device__ int   g_unit_ctr;

__device__ bf16 g_xt_h   [(size_t)NROWS * CDM];
__device__ bf16 g_xt_l   [(size_t)NROWS * CDM];
__device__ bf16 g_wall_h [(size_t)4096 * 1024];   // Wq^T | Wkvg^T
__device__ bf16 g_wall_l [(size_t)4096 * 1024];
__device__ bf16 g_wrest_h[(size_t)1024 * 1024];
__device__ bf16 g_wrest_l[(size_t)1024 * 1024];
__device__ bf16 g_qu_h   [(size_t)NBH * CL * CDK];
__device__ bf16 g_qu_l   [(size_t)NBH * CL * CDK];
__device__ bf16 g_qv_h   [(size_t)NBH * CL * CDK];
__device__ bf16 g_qv_l   [(size_t)NBH * CL * CDK];
__device__ bf16 g_kl_h   [(size_t)NBH * CL * CDK];
__device__ bf16 g_kl_l   [(size_t)NBH * CL * CDK];
__device__ bf16 g_khat_h [(size_t)NBH * CM * CDK];
__device__ bf16 g_khat_l [(size_t)NBH * CM * CDK];
__device__ bf16 g_cb_h   [(size_t)CH * CS * CDK];
__device__ bf16 g_cb_l   [(size_t)CH * CS * CDK];
__device__ bf16 g_xlr_h  [(size_t)CH * CW * CDK];
__device__ bf16 g_xlr_l  [(size_t)CH * CW * CDK];
__device__ bf16 g_vt_h   [(size_t)NBH * CDV * SCW];
__device__ bf16 g_vt_l   [(size_t)NBH * CDV * SCW];
__device__ bf16 g_wvg_h  [(size_t)NROWS * CDM];
__device__ bf16 g_wvg_l  [(size_t)NROWS * CDM];

// ---------------------------------------------------------------------------
// primitives
// ---------------------------------------------------------------------------
__device__ __forceinline__ uint32_t cvta_s(const void* p) {
    return (uint32_t)__cvta_generic_to_shared(p);
}
__device__ __forceinline__ void ldmx4(uint32_t addr, uint32_t& r0, uint32_t& r1,
                                      uint32_t& r2, uint32_t& r3) {
    asm volatile("ldmatrix.sync.aligned.m8n8.x4.shared.b16 {%0,%1,%2,%3}, [%4];"
                 : "=r"(r0), "=r"(r1), "=r"(r2), "=r"(r3) : "r"(addr));
}
__device__ __forceinline__ void mma16816(float c[4], const uint32_t a[4], const uint32_t b[2]) {
    asm volatile(
        "mma.sync.aligned.m16n8k16.row.col.f32.bf16.bf16.f32 "
        "{%0,%1,%2,%3}, {%4,%5,%6,%7}, {%8,%9}, {%0,%1,%2,%3};"
        : "+f"(c[0]), "+f"(c[1]), "+f"(c[2]), "+f"(c[3])
        : "r"(a[0]), "r"(a[1]), "r"(a[2]), "r"(a[3]), "r"(b[0]), "r"(b[1]));
}
__device__ __forceinline__ void cpa16(uint32_t d, const void* s) {
    asm volatile("cp.async.ca.shared.global [%0], [%1], 16;" :: "r"(d), "l"(s));
}
__device__ __forceinline__ void cpa_commit() {
    asm volatile("cp.async.commit_group;");
}
template <int NN>
__device__ __forceinline__ void cpa_wait() {
    asm volatile("cp.async.wait_group %0;" :: "n"(NN));
}

__device__ __forceinline__ void splitw(float x, bf16* h, bf16* l) {
    bf16 hh = __float2bfloat16_rn(x);
    *h = hh;
    *l = __float2bfloat16_rn(x - __bfloat162float(hh));
}
__device__ __forceinline__ void split4(float4 v, bf16* hp, bf16* lp) {
    __nv_bfloat162 h0 = __floats2bfloat162_rn(v.x, v.y);
    __nv_bfloat162 h1 = __floats2bfloat162_rn(v.z, v.w);
    float2 f0 = __bfloat1622float2(h0);
    float2 f1 = __bfloat1622float2(h1);
    __nv_bfloat162 l0 = __floats2bfloat162_rn(v.x - f0.x, v.y - f0.y);
    __nv_bfloat162 l1 = __floats2bfloat162_rn(v.z - f1.x, v.w - f1.y);
    uint2 hv, lv;
    hv.x = *(uint32_t*)&h0; hv.y = *(uint32_t*)&h1;
    lv.x = *(uint32_t*)&l0; lv.y = *(uint32_t*)&l1;
    *(uint2*)hp = hv;
    *(uint2*)lp = lv;
}
__device__ __forceinline__ uint32_t packbf(float x, float y) {
    __nv_bfloat162 t = __floats2bfloat162_rn(x, y);
    return *(uint32_t*)&t;
}
__device__ __forceinline__ uint32_t packbf_res(float x, float y, uint32_t hp) {
    __nv_bfloat162 hv = *(__nv_bfloat162*)&hp;
    float2 f = __bfloat1622float2(hv);
    return packbf(x - f.x, y - f.y);
}

// ---------------------------------------------------------------------------
// reductions
// ---------------------------------------------------------------------------
__device__ __forceinline__ float block_sum(float v) {
    __shared__ float sb_[8];
    int tid = threadIdx.x;
    int nw  = blockDim.x >> 5;
    #pragma unroll
    for (int o = 16; o; o >>= 1) v += __shfl_down_sync(0xffffffffu, v, o);
    __syncthreads();
    if ((tid & 31) == 0) sb_[tid >> 5] = v;
    __syncthreads();
    float r = 0.f;
    for (int i = 0; i < nw; ++i) r += sb_[i];
    return r;
}
__device__ __forceinline__ float warp_sum(float v) {
    #pragma unroll
    for (int o = 16; o; o >>= 1) v += __shfl_xor_sync(0xffffffffu, v, o);
    return v;
}

// ---------------------------------------------------------------------------
// Fused preprocessing (one launch, all light blocks)
// ---------------------------------------------------------------------------
#define PS0 1024
#define PS1 (PS0 + 3072)
#define PS2 (PS1 + 1024)
#define PS3 (PS2 + 4096)
#define PS4 (PS3 + 512)
#define PS5 (PS4 + 1024)
#define PS6 (PS5 + 4096)
#define PS7 (PS6 + 512)
#define PS8 (PS7 + 32)
#define PREP_GRID PS8

__device__ __forceinline__ void do_transpose(const float* __restrict__ src,
                                             bf16* __restrict__ dh,
                                             bf16* __restrict__ dl,
                                             int R, int C, int id,
                                             float (*tile)[33]) {
    int bx = id % (C >> 5), by = id / (C >> 5);
    int c0 = bx * 32, r0 = by * 32;
    int x = threadIdx.x & 31, y = (threadIdx.x >> 5) * 4;
    #pragma unroll
    for (int i = 0; i < 4; ++i)
        tile[y + i][x] = src[(size_t)(r0 + y + i) * C + c0 + x];
    __syncthreads();
    #pragma unroll
    for (int i = 0; i < 4; ++i) {
        size_t o = (size_t)(c0 + y + i) * R + r0 + x;
        splitw(tile[x][y + i], dh + o, dl + o);
    }
}
__device__ __forceinline__ void do_convert(const float* __restrict__ src,
                                           bf16* __restrict__ h,
                                           bf16* __restrict__ l, int id) {
    size_t idx = (size_t)id * 256 + threadIdx.x;
    float4 v = ((const float4*)src)[idx];
    split4(v, h + idx * 4, l + idx * 4);
}

__global__ void __launch_bounds__(256) prep_kernel(
    const float* __restrict__ W_q, const float* __restrict__ W_kvg,
    const float* __restrict__ W_res,
    const float* __restrict__ xl_k_hat, const float* __restrict__ codebook,
    const float* __restrict__ xl_r, const float* __restrict__ input,
    bf16* wall_h, bf16* wall_l, bf16* wrest_h, bf16* wrest_l,
    bf16* khat_h, bf16* khat_l, bf16* cb_h, bf16* cb_l,
    bf16* xlr_h, bf16* xlr_l, bf16* xt_h, bf16* xt_l,
    float* csq, unsigned long long* zpk, int* ctr) {

    __shared__ float tile[32][33];
    int bid = blockIdx.x;
    int tid = threadIdx.x;

    if (bid < PS0) {
        do_transpose(W_q, wall_h, wall_l, 1024, 1024, bid, tile);
    } else if (bid < PS1) {
        do_transpose(W_kvg, wall_h + (size_t)1024 * 1024, wall_l + (size_t)1024 * 1024,
                     1024, 3072, bid - PS0, tile);
    } else if (bid < PS2) {
        do_transpose(W_res, wrest_h, wrest_l, 1024, 1024, bid - PS1, tile);
    } else if (bid < PS3) {
        do_convert(xl_k_hat, khat_h, khat_l, bid - PS2);
    } else if (bid < PS4) {
        do_convert(codebook, cb_h, cb_l, bid - PS3);
    } else if (bid < PS5) {
        do_convert(xl_r, xlr_h, xlr_l, bid - PS4);
    } else if (bid < PS6) {
        int row = bid - PS5;
        const float* xr = input + (size_t)row * CDM;
        float4 v = *(const float4*)(xr + tid * 4);
        float s = v.x + v.y + v.z + v.w;
        float mu = block_sum(s) * (1.f / 1024.f);
        v.x -= mu; v.y -= mu; v.z -= mu; v.w -= mu;
        float s2 = v.x * v.x + v.y * v.y + v.z * v.z + v.w * v.w;
        float rstd = rsqrtf(block_sum(s2) * (1.f / 1024.f) + 1e-6f);
        v.x *= rstd; v.y *= rstd; v.z *= rstd; v.w *= rstd;
        split4(v, xt_h + (size_t)row * CDM + tid * 4, xt_l + (size_t)row * CDM + tid * 4);
    } else if (bid < PS7) {
        int wid  = tid >> 5, lane = tid & 31;
        int row = (bid - PS6) * 8 + wid;
        float4 v = *(const float4*)(codebook + (size_t)row * CDK + lane * 4);
        float s = warp_sum(v.x * v.x + v.y * v.y + v.z * v.z + v.w * v.w);
        if (lane == 0) csq[row] = s;
    } else {
        int id = bid - PS7;
        size_t base = (size_t)id * 1024 + tid * 4;
        zpk[base + 0] = ~0ull; zpk[base + 1] = ~0ull;
        zpk[base + 2] = ~0ull; zpk[base + 3] = ~0ull;
        if (id == 0 && tid == 0) *ctr = 0;
    }
}

// ---------------------------------------------------------------------------
// Vt gather-transpose: 32v x 64w tiles, 128B-coalesced loads AND stores
// ---------------------------------------------------------------------------
__global__ void __launch_bounds__(256) vt_kernel(const float* __restrict__ xl_v,
                                                 const float* __restrict__ vv,
                                                 const float* __restrict__ aggu,
                                                 bf16* __restrict__ vth,
                                                 bf16* __restrict__ vtl) {
    __shared__ float tile[64][33];   // [w][v]
    int zb = blockIdx.z;
    int w0 = blockIdx.x * 64, v0 = blockIdx.y * 32;
    int tid = threadIdx.x;
    int lane = tid & 31, warp = tid >> 5;

    // load: each warp reads one w-row (32 consecutive v floats = 128B)
    #pragma unroll
    for (int i = 0; i < 8; ++i) {
        int w = w0 + warp + i * 8;
        const float* srcrow;
        if (w < CM)      srcrow = xl_v + ((size_t)zb * CM + w) * CDV;
        else if (w < CW) srcrow = vv   + ((size_t)zb * CL + (w - CM)) * CDV;
        else             srcrow = aggu + ((size_t)zb * CS + (w - CW)) * CDV;
        tile[warp + i * 8][lane] = srcrow[v0 + lane];
    }
    __syncthreads();

    // store: each warp writes v-rows; lane covers 2 w's -> 128B per plane
    #pragma unroll
    for (int i = 0; i < 4; ++i) {
        int v = warp * 4 + i;
        float x0 = tile[2 * lane][v];
        float x1 = tile[2 * lane + 1][v];
        uint32_t hp = packbf(x0, x1);
        uint32_t lp = packbf_res(x0, x1, hp);
        size_t o = (((size_t)zb * CDV + v0 + v) * SCW + w0) >> 1;
        ((uint32_t*)vth)[o + lane] = hp;
        ((uint32_t*)vtl)[o + lane] = lp;
    }
}

// ---------------------------------------------------------------------------
// per-(b,l,h) transform (reads fused proj buffer)
// ---------------------------------------------------------------------------
__global__ void __launch_bounds__(256) transform_kernel(const float* __restrict__ proj,
                                                        const float* __restrict__ x_u,
                                                        const float* __restrict__ x_v,
                                                        bf16* __restrict__ quh, bf16* __restrict__ qul,
                                                        bf16* __restrict__ qvh, bf16* __restrict__ qvl,
                                                        bf16* __restrict__ klh, bf16* __restrict__ kll,
                                                        float* __restrict__ vv,
                                                        float* __restrict__ gate) {
    int wid  = threadIdx.x >> 5;
    int lane = threadIdx.x & 31;
    int idx = blockIdx.x * 8 + wid;
    int h  = idx & 7;
    int bl = idx >> 3;
    int b = bl >> 9, l = bl & 511;
    int d0 = lane * 4;
    const float* prow = proj + (size_t)bl * 4096 + h * CDK + d0;

    float4 q = *(const float4*)(prow);
    float mu = warp_sum(q.x + q.y + q.z + q.w) * (1.f / 128.f);
    q.x -= mu; q.y -= mu; q.z -= mu; q.w -= mu;
    float var = warp_sum(q.x * q.x + q.y * q.y + q.z * q.z + q.w * q.w) * (1.f / 128.f);
    float rs = rsqrtf(var + 1e-6f);
    float4 xu = *(const float4*)(x_u + h * CDK + d0);
    float4 xv = *(const float4*)(x_v + h * CDK + d0);
    size_t o = (((size_t)b * CH + h) * CL + l) * CDK + d0;
    split4(make_float4(q.x * rs + xu.x, q.y * rs + xu.y, q.z * rs + xu.z, q.w * rs + xu.w),
           quh + o, qul + o);
    split4(make_float4(q.x * rs + xv.x, q.y * rs + xv.y, q.z * rs + xv.z, q.w * rs + xv.w),
           qvh + o, qvl + o);

    float4 k = *(const float4*)(prow + 1024);
    float kmu = warp_sum(k.x + k.y + k.z + k.w) * (1.f / 128.f);
    k.x -= kmu; k.y -= kmu; k.z -= kmu; k.w -= kmu;
    float kvar = warp_sum(k.x * k.x + k.y * k.y + k.z * k.z + k.w * k.w) * (1.f / 128.f);
    float krs = rsqrtf(kvar + 1e-6f);
    split4(make_float4(k.x * krs, k.y * krs, k.z * krs, k.w * krs), klh + o, kll + o);

    *(float4*)(vv + o) = *(const float4*)(prow + 2048);

    float4 gg = *(const float4*)(prow + 3072);
    float4 gs;
    gs.x = gg.x / (1.f + __expf(-gg.x));
    gs.y = gg.y / (1.f + __expf(-gg.y));
    gs.z = gg.z / (1.f + __expf(-gg.z));
    gs.w = gg.w / (1.f + __expf(-gg.w));
    *(float4*)(gate + (size_t)bl * CDM + h * CDK + d0) = gs;
}

// ---------------------------------------------------------------------------
// NT tensor-core GEMM body (bf16x3, 3-stage cp.async). MODE: 0=BD, 3=VQ, 4=PROJ
// ---------------------------------------------------------------------------
#define STG_B 12288
#define CMP_B 6144
#define SBOFF 36864
template <int MODE>
__device__ __forceinline__ void gemm_body(
    char* smem, int bm, int bn, int bh,
    const bf16* __restrict__ Ah, const bf16* __restrict__ Al,
    const bf16* __restrict__ Bh, const bf16* __restrict__ Bl,
    const float* __restrict__ csq,
    unsigned long long* zpk_out,
    float* __restrict__ outp,
    int N, int K, int lda) {

    int tid  = threadIdx.x;
    int lane = tid & 31, warp = tid >> 5;
    int wm = warp >> 2, wn = warp & 3;
    int h  = bh & 7;

    if (MODE == 0 && (bn + bm) < 257) return;   // BD dead tiles

    size_t aoff = (MODE == 4) ? 0 : (size_t)bh * CL * CDK;

    int srow = tid >> 1;
    int sc8  = (tid & 1) * 8;
    const bf16* a_h = Ah + aoff + (size_t)(bm + srow) * lda + sc8;
    const bf16* a_l = Al + aoff + (size_t)(bm + srow) * lda + sc8;
    const bf16 *b_h, *b_l;
    {
        int n = bn + srow;
        size_t boff;
        if (MODE == 0)      boff = ((size_t)h * CW + n) * CDK;
        else if (MODE == 3) boff = ((size_t)h * CS + n) * CDK;
        else                boff = (size_t)n * K;
        b_h = Bh + boff + sc8; b_l = Bl + boff + sc8;
    }

    uint32_t sA = cvta_s(smem);
    uint32_t sB = sA + SBOFF;
    uint32_t dA = sA + (uint32_t)(srow * 24 + sc8) * 2;
    uint32_t dB = sB + (uint32_t)(srow * 24 + sc8) * 2;

    int a_off = (wm * 64 + (lane & 15)) * 24 + ((lane >> 4) << 3);
    int b_off = (wn * 32 + ((lane >> 4) << 3) + (lane & 7)) * 24 + (((lane >> 3) & 1) << 3);

    float acc[4][4][4] = {};
    int T = K >> 4;

    cpa16(dA,         a_h);  cpa16(dA + CMP_B, a_l);
    cpa16(dB,         b_h);  cpa16(dB + CMP_B, b_l);
    cpa_commit();

    #pragma unroll 1
    for (int kt = 0; kt < T; ++kt) {
        if (kt + 1 < T) {
            int st = (kt + 1) % 3;
            int k0 = (kt + 1) * 16;
            cpa16(dA + st * STG_B,         a_h + k0);
            cpa16(dA + st * STG_B + CMP_B, a_l + k0);
            cpa16(dB + st * STG_B,         b_h + k0);
            cpa16(dB + st * STG_B + CMP_B, b_l + k0);
            cpa_commit();
            cpa_wait<1>();
        } else {
            cpa_wait<0>();
        }
        __syncthreads();

        int cs = kt % 3;
        uint32_t aH = sA + cs * STG_B + (uint32_t)a_off * 2;
        uint32_t bH = sB + cs * STG_B + (uint32_t)b_off * 2;
        uint32_t ah[4][4], al[4][4], bhf[4][2], blf[4][2];
        #pragma unroll
        for (int t = 0; t < 4; ++t) {
            ldmx4(aH + t * 768,         ah[t][0], ah[t][1], ah[t][2], ah[t][3]);
            ldmx4(aH + CMP_B + t * 768, al[t][0], al[t][1], al[t][2], al[t][3]);
        }
        #pragma unroll
        for (int u2 = 0; u2 < 2; ++u2) {
            uint32_t r0, r1, r2, r3;
            ldmx4(bH + u2 * 768, r0, r1, r2, r3);
            bhf[2 * u2][0] = r0; bhf[2 * u2][1] = r1;
            bhf[2 * u2 + 1][0] = r2; bhf[2 * u2 + 1][1] = r3;
            ldmx4(bH + CMP_B + u2 * 768, r0, r1, r2, r3);
            blf[2 * u2][0] = r0; blf[2 * u2][1] = r1;
            blf[2 * u2 + 1][0] = r2; blf[2 * u2 + 1][1] = r3;
        }
        #pragma unroll
        for (int t = 0; t < 4; ++t)
            #pragma unroll
            for (int u = 0; u < 4; ++u) {
                mma16816(acc[t][u], ah[t], bhf[u]);
                mma16816(acc[t][u], ah[t], blf[u]);
                mma16816(acc[t][u], al[t], bhf[u]);
            }
    }

    int g  = lane >> 2;
    int qd = lane & 3;

    if constexpr (MODE == 4) {
        #pragma unroll
        for (int t = 0; t < 4; ++t) {
            int r = bm + wm * 64 + t * 16 + g;
            #pragma unroll
            for (int u = 0; u < 4; ++u) {
                int c = bn + wn * 32 + u * 8 + qd * 2;
                *(float2*)(outp + (size_t)r * N + c) =
                    make_float2(acc[t][u][0], acc[t][u][1]);
                *(float2*)(outp + (size_t)(r + 8) * N + c) =
                    make_float2(acc[t][u][2], acc[t][u][3]);
            }
        }
    } else if constexpr (MODE == 0) {
        #pragma unroll
        for (int t = 0; t < 4; ++t) {
            int l = bm + wm * 64 + t * 16 + g;
            #pragma unroll
            for (int u = 0; u < 4; ++u) {
                int c = bn + wn * 32 + u * 8 + qd * 2;
                *(float2*)(outp + ((size_t)bh * CL + l) * CW + c) =
                    make_float2(acc[t][u][0] * TAUI, acc[t][u][1] * TAUI);
                *(float2*)(outp + ((size_t)bh * CL + l + 8) * CW + c) =
                    make_float2(acc[t][u][2] * TAUI, acc[t][u][3] * TAUI);
            }
        }
    } else {   // VQ argmin
        unsigned long long* zmin = reinterpret_cast<unsigned long long*>(smem);
        __syncthreads();
        if (tid < 128) zmin[tid] = ~0ull;
        __syncthreads();
        #pragma unroll
        for (int t = 0; t < 4; ++t) {
            unsigned long long b0 = ~0ull, b1 = ~0ull;
            #pragma unroll
            for (int u = 0; u < 4; ++u) {
                #pragma unroll
                for (int p = 0; p < 2; ++p) {
                    int s = bn + wn * 32 + u * 8 + qd * 2 + p;
                    float cs = csq[h * CS + s];
                    {
                        float val = cs - 2.f * acc[t][u][p];
                        unsigned uu = __float_as_uint(val);
                        uu = (uu & 0x80000000u) ? ~uu : (uu | 0x80000000u);
                        unsigned long long key = ((unsigned long long)uu << 32) | (unsigned)s;
                        if (key < b0) b0 = key;
                    }
                    {
                        float val = cs - 2.f * acc[t][u][2 + p];
                        unsigned uu = __float_as_uint(val);
                        uu = (uu & 0x80000000u) ? ~uu : (uu | 0x80000000u);
                        unsigned long long key = ((unsigned long long)uu << 32) | (unsigned)s;
                        if (key < b1) b1 = key;
                    }
                }
            }
            unsigned long long o;
            o = __shfl_xor_sync(0xffffffffu, b0, 1); if (o < b0) b0 = o;
            o = __shfl_xor_sync(0xffffffffu, b0, 2); if (o < b0) b0 = o;
            o = __shfl_xor_sync(0xffffffffu, b1, 1); if (o < b1) b1 = o;
            o = __shfl_xor_sync(0xffffffffu, b1, 2); if (o < b1) b1 = o;
            if (qd == 0) {
                atomicMin(&zmin[wm * 64 + t * 16 + g], b0);
                atomicMin(&zmin[wm * 64 + t * 16 + g + 8], b1);
            }
        }
        __syncthreads();
        if (tid < 128)
            atomicMin(&zpk_out[(size_t)bh * CL + bm + tid], zmin[tid]);
    }
}

// wrapper kernels
__global__ void __launch_bounds__(256) mma_gemm4_kernel(
    const bf16* __restrict__ Ah, const bf16* __restrict__ Al,
    const bf16* __restrict__ Bh, const bf16* __restrict__ Bl,
    float* __restrict__ outp, int N, int K, int lda) {
    __shared__ __align__(16) char smem[73728];
    gemm_body<4>(smem, blockIdx.y * 128, blockIdx.x * 128, 0,
                 Ah, Al, Bh, Bl, nullptr, nullptr, outp, N, K, lda);
}

// merged VQ + BD (footprint-homogeneous GEMM blocks)
#define VB_VQ 1024
#define VB_END 3072
__global__ void __launch_bounds__(256) vqbd_kernel(
    const bf16* __restrict__ kl_h, const bf16* __restrict__ kl_l,
    const bf16* __restrict__ qv_h, const bf16* __restrict__ qv_l,
    const bf16* __restrict__ cb_h, const bf16* __restrict__ cb_l,
    const bf16* __restrict__ xlr_h, const bf16* __restrict__ xlr_l,
    const float* __restrict__ csq, unsigned long long* zpk,
    float* __restrict__ rbd) {
    __shared__ __align__(16) char smem[73728];
    int bid = blockIdx.x;
    if (bid < VB_VQ) {
        int x = bid & 3, y = (bid >> 2) & 3, z = bid >> 4;
        gemm_body<3>(smem, y * 128, x * 128, z, kl_h, kl_l, cb_h, cb_l,
                     csq, zpk, nullptr, 512, 128, 128);
    } else {
        int id = bid - VB_VQ;
        int x = id & 7, y = (id >> 3) & 3, z = id >> 5;
        gemm_body<0>(smem, y * 128, x * 128, z, qv_h, qv_l, xlr_h, xlr_l,
                     nullptr, nullptr, rbd, 1024, 128, 128);
    }
}

// ---------------------------------------------------------------------------
// Fused attention (persistent, work-stealing, heavy units first)
// ---------------------------------------------------------------------------
#define APITCH 272
#define APLANE 34816
#define ABUF   69632
#define NUNITS 256
__global__ void __launch_bounds__(256) attn_kernel(
    const bf16* __restrict__ quh, const bf16* __restrict__ qul,
    const bf16* __restrict__ khat_h, const bf16* __restrict__ khat_l,
    const bf16* __restrict__ cb_h, const bf16* __restrict__ cb_l,
    const bf16* __restrict__ vt_h, const bf16* __restrict__ vt_l,
    const unsigned long long* __restrict__ zpk,
    const float* __restrict__ rbd,
    const float* __restrict__ agg_lower,
    const float* __restrict__ gate,
    int* __restrict__ unit_ctr,
    bf16* __restrict__ outh, bf16* __restrict__ outl) {

    extern __shared__ __align__(16) char smem_raw[];
    uint32_t sQU = cvta_s(smem_raw);
    uint32_t sKT = sQU + ABUF;
    uint32_t sVT = sQU + 2 * ABUF;
    __shared__ int s_unit;

    int tid  = threadIdx.x;
    int lane = tid & 31, warp = tid >> 5;
    int g = lane >> 2, qd = lane & 3;

    for (;;) {
        __syncthreads();
        if (tid == 0) s_unit = atomicAdd(unit_ctr, 1);
        __syncthreads();
        int unit = s_unit;
        if (unit >= NUNITS) break;

        int bm = (3 - (unit >> 6)) * 128;    // heavy units (bm=384) first
        int bh = unit & 63;
        int h  = bh & 7;
        int b  = bh >> 3;

        int tiles[12]; int nt = 0;
        #pragma unroll
        for (int j = 0; j < 12; ++j)
            if (!(j < 8 && j * 128 >= bm + CM + 128)) tiles[nt++] = j;

        auto load_qu = [&]() {
            size_t qoff = (size_t)bh * CL * CDK;
            #pragma unroll
            for (int i = 0; i < 8; ++i) {
                int id = tid + i * 256;
                int r = id >> 4, c = id & 15;
                uint32_t d = sQU + r * APITCH + c * 16;
                cpa16(d,          quh + qoff + (size_t)(bm + r) * CDK + c * 8);
                cpa16(d + APLANE, qul + qoff + (size_t)(bm + r) * CDK + c * 8);
            }
        };
        auto load_kt = [&](int j) {
            #pragma unroll
            for (int i = 0; i < 8; ++i) {
                int id = tid + i * 256;
                int r = id >> 4, c = id & 15;
                int n = j * 128 + r;
                const bf16 *sh, *sl;
                if (j < 4) {
                    size_t o = ((size_t)bh * CM + n) * CDK;
                    sh = khat_h + o; sl = khat_l + o;
                } else if (j < 8) {
                    unsigned zi = (unsigned)(zpk[(size_t)bh * CL + (n - CM)] & 0xffffffffull);
                    size_t o = ((size_t)h * CS + zi) * CDK;
                    sh = cb_h + o; sl = cb_l + o;
                } else {
                    size_t o = ((size_t)h * CS + (n - CW)) * CDK;
                    sh = cb_h + o; sl = cb_l + o;
                }
                uint32_t d = sKT + r * APITCH + c * 16;
                cpa16(d,          sh + c * 8);
                cpa16(d + APLANE, sl + c * 8);
            }
        };
        auto load_vt = [&](int j) {
            #pragma unroll
            for (int i = 0; i < 8; ++i) {
                int id = tid + i * 256;
                int r = id >> 4, c = id & 15;
                size_t o = ((size_t)bh * CDV + r) * SCW + j * 128 + c * 8;
                uint32_t d = sVT + r * APITCH + c * 16;
                cpa16(d,          vt_h + o);
                cpa16(d + APLANE, vt_l + o);
            }
        };

        uint32_t quB = sQU + (uint32_t)(warp * 16 + (lane & 15)) * APITCH + ((lane >> 4) << 4);
        uint32_t bB  = (uint32_t)((((lane >> 4) << 3) + (lane & 7)) * APITCH) + (((lane >> 3) & 1) << 4);

        int l0 = bm + warp * 16 + g;
        int l1 = l0 + 8;

        float O[16][4] = {};
        float m0 = -3.4e38f, m1 = -3.4e38f, d0 = 0.f, d1 = 0.f;

        load_qu();
        load_kt(tiles[0]);
        cpa_commit();

        #pragma unroll 1
        for (int ti = 0; ti < nt; ++ti) {
            int j = tiles[ti];
            cpa_wait<0>();
            __syncthreads();
            load_vt(j);
            cpa_commit();

            float S[16][4] = {};
            #pragma unroll
            for (int kg = 0; kg < 8; ++kg) {
                uint32_t ah[4], al[4];
                ldmx4(quB + kg * 32,          ah[0], ah[1], ah[2], ah[3]);
                ldmx4(quB + APLANE + kg * 32, al[0], al[1], al[2], al[3]);
                #pragma unroll
                for (int nf = 0; nf < 8; ++nf) {
                    uint32_t base = sKT + bB + nf * (16 * APITCH) + kg * 32;
                    uint32_t p0, p1, p2, p3, q0, q1, q2, q3;
                    ldmx4(base,          p0, p1, p2, p3);
                    ldmx4(base + APLANE, q0, q1, q2, q3);
                    uint32_t bp[2], bq[2];
                    bp[0] = p0; bp[1] = p1; bq[0] = q0; bq[1] = q1;
                    mma16816(S[nf * 2], ah, bp);
                    mma16816(S[nf * 2], ah, bq);
                    mma16816(S[nf * 2], al, bp);
                    bp[0] = p2; bp[1] = p3; bq[0] = q2; bq[1] = q3;
                    mma16816(S[nf * 2 + 1], ah, bp);
                    mma16816(S[nf * 2 + 1], ah, bq);
                    mma16816(S[nf * 2 + 1], al, bp);
                }
            }

            if (j < 8) {
                const float* rr0 = rbd + ((size_t)bh * CL + l0) * CW + (CL - 1) - l0;
                const float* rr1 = rbd + ((size_t)bh * CL + l1) * CW + (CL - 1) - l1;
                int wb = j * 128 + qd * 2;
                #pragma unroll
                for (int u = 0; u < 16; ++u) {
                    int w = wb + u * 8;
                    S[u][0] = (w     <= l0 + CM) ? S[u][0] * TAUI + rr0[w]     : -1e30f;
                    S[u][1] = (w + 1 <= l0 + CM) ? S[u][1] * TAUI + rr0[w + 1] : -1e30f;
                    S[u][2] = (w     <= l1 + CM) ? S[u][2] * TAUI + rr1[w]     : -1e30f;
                    S[u][3] = (w + 1 <= l1 + CM) ? S[u][3] * TAUI + rr1[w + 1] : -1e30f;
                }
            } else {
                int sb = (j - 8) * 128 + qd * 2;
                #pragma unroll
                for (int u = 0; u < 16; ++u) {
                    int s = sb + u * 8;
                    float a0 = agg_lower[(size_t)bh * CS + s];
                    float a1 = agg_lower[(size_t)bh * CS + s + 1];
                    float b0 = (a0 > 0.f) ? logf(fmaxf(a0, 1e-30f)) : -1e30f;
                    float b1 = (a1 > 0.f) ? logf(fmaxf(a1, 1e-30f)) : -1e30f;
                    S[u][0] = S[u][0] * TAUI + b0;
                    S[u][1] = S[u][1] * TAUI + b1;
                    S[u][2] = S[u][2] * TAUI + b0;
                    S[u][3] = S[u][3] * TAUI + b1;
                }
            }

            float mx0 = -3.4e38f, mx1 = -3.4e38f;
            #pragma unroll
            for (int u = 0; u < 16; ++u) {
                mx0 = fmaxf(mx0, fmaxf(S[u][0], S[u][1]));
                mx1 = fmaxf(mx1, fmaxf(S[u][2], S[u][3]));
            }
            mx0 = fmaxf(mx0, __shfl_xor_sync(0xffffffffu, mx0, 1));
            mx0 = fmaxf(mx0, __shfl_xor_sync(0xffffffffu, mx0, 2));
            mx1 = fmaxf(mx1, __shfl_xor_sync(0xffffffffu, mx1, 1));
            mx1 = fmaxf(mx1, __shfl_xor_sync(0xffffffffu, mx1, 2));
            float nm0 = fmaxf(m0, mx0), nm1 = fmaxf(m1, mx1);
            float al0 = __expf(m0 - nm0), al1 = __expf(m1 - nm1);
            m0 = nm0; m1 = nm1;
            float s0 = 0.f, s1 = 0.f;
            #pragma unroll
            for (int u = 0; u < 16; ++u) {
                S[u][0] = __expf(S[u][0] - m0);
                S[u][1] = __expf(S[u][1] - m0);
                S[u][2] = __expf(S[u][2] - m1);
                S[u][3] = __expf(S[u][3] - m1);
                s0 += S[u][0] + S[u][1];
                s1 += S[u][2] + S[u][3];
            }
            s0 += __shfl_xor_sync(0xffffffffu, s0, 1);
            s0 += __shfl_xor_sync(0xffffffffu, s0, 2);
            s1 += __shfl_xor_sync(0xffffffffu, s1, 1);
            s1 += __shfl_xor_sync(0xffffffffu, s1, 2);
            d0 = d0 * al0 + s0;
            d1 = d1 * al1 + s1;
            #pragma unroll
            for (int u = 0; u < 16; ++u) {
                O[u][0] *= al0; O[u][1] *= al0;
                O[u][2] *= al1; O[u][3] *= al1;
            }

            cpa_wait<0>();
            __syncthreads();
            if (ti + 1 < nt) { load_kt(tiles[ti + 1]); cpa_commit(); }

            #pragma unroll
            for (int kg = 0; kg < 8; ++kg) {
                int u2 = kg * 2;
                uint32_t pah[4], pal[4];
                pah[0] = packbf(S[u2][0], S[u2][1]);
                pah[1] = packbf(S[u2][2], S[u2][3]);
                pah[2] = packbf(S[u2 + 1][0], S[u2 + 1][1]);
                pah[3] = packbf(S[u2 + 1][2], S[u2 + 1][3]);
                pal[0] = packbf_res(S[u2][0], S[u2][1], pah[0]);
                pal[1] = packbf_res(S[u2][2], S[u2][3], pah[1]);
                pal[2] = packbf_res(S[u2 + 1][0], S[u2 + 1][1], pah[2]);
                pal[3] = packbf_res(S[u2 + 1][2], S[u2 + 1][3], pah[3]);
                #pragma unroll
                for (int nf = 0; nf < 8; ++nf) {
                    uint32_t base = sVT + bB + nf * (16 * APITCH) + kg * 32;
                    uint32_t p0, p1, p2, p3, q0, q1, q2, q3;
                    ldmx4(base,          p0, p1, p2, p3);
                    ldmx4(base + APLANE, q0, q1, q2, q3);
                    uint32_t bp[2], bq[2];
                    bp[0] = p0; bp[1] = p1; bq[0] = q0; bq[1] = q1;
                    mma16816(O[nf * 2], pah, bp);
                    mma16816(O[nf * 2], pah, bq);
                    mma16816(O[nf * 2], pal, bp);
                    bp[0] = p2; bp[1] = p3; bq[0] = q2; bq[1] = q3;
                    mma16816(O[nf * 2 + 1], pah, bp);
                    mma16816(O[nf * 2 + 1], pah, bq);
                    mma16816(O[nf * 2 + 1], pal, bp);
                }
            }
        }

        float i0 = 1.f / d0, i1 = 1.f / d1;
        #pragma unroll
        for (int u = 0; u < 16; ++u) {
            int c = (u << 3) + qd * 2;
            size_t o0 = ((size_t)b * CL + l0) * CDM + h * CDV + c;
            size_t o1 = ((size_t)b * CL + l1) * CDM + h * CDV + c;
            float2 g0 = *(const float2*)(gate + o0);
            float2 g1 = *(const float2*)(gate + o1);
            splitw(O[u][0] * i0 * g0.x, outh + o0,     outl + o0);
            splitw(O[u][1] * i0 * g0.y, outh + o0 + 1, outl + o0 + 1);
            splitw(O[u][2] * i1 * g1.x, outh + o1,     outl + o1);
            splitw(O[u][3] * i1 * g1.y, outh + o1 + 1, outl + o1 + 1);
        }
    }
}

// ---------------------------------------------------------------------------
// Host launcher
// ---------------------------------------------------------------------------
#define SMEM_ATTN (3 * ABUF)
#define ATTN_GRID 148

extern "C" void kernel_launch(void* const* d_in, const int* in_sizes, int n_in,
                              void* d_out, int out_size) {
    const float* input     = (const float*)d_in[0];
    const float* xl_k_hat  = (const float*)d_in[2];
    const float* xl_v      = (const float*)d_in[3];
    const float* agg_upper = (const float*)d_in[4];
    const float* agg_lower = (const float*)d_in[5];
    const float* W_q       = (const float*)d_in[6];
    const float* W_kvg     = (const float*)d_in[7];
    const float* W_res     = (const float*)d_in[8];
    const float* x_u       = (const float*)d_in[9];
    const float* x_v       = (const float*)d_in[10];
    const float* xl_r      = (const float*)d_in[11];
    const float* codebook  = (const float*)d_in[12];
    float* out = (float*)d_out;

    float *proj, *vv, *gate, *rbd, *csq;
    unsigned long long* zpk;
    int* ctr;
    bf16 *xt_h, *xt_l, *wall_h, *wall_l, *wrest_h, *wrest_l;
    bf16 *qu_h, *qu_l, *qv_h, *qv_l, *kl_h, *kl_l, *khat_h, *khat_l;
    bf16 *cb_h, *cb_l, *xlr_h, *xlr_l, *vt_h, *vt_l, *wvg_h, *wvg_l;

    cudaGetSymbolAddress((void**)&proj, g_proj);
    cudaGetSymbolAddress((void**)&vv, g_vv);
    cudaGetSymbolAddress((void**)&gate, g_gate);
    cudaGetSymbolAddress((void**)&rbd, g_rbd);
    cudaGetSymbolAddress((void**)&csq, g_csq);
    cudaGetSymbolAddress((void**)&zpk, g_zpk);
    cudaGetSymbolAddress((void**)&ctr, g_unit_ctr);
    cudaGetSymbolAddress((void**)&xt_h, g_xt_h);   cudaGetSymbolAddress((void**)&xt_l, g_xt_l);
    cudaGetSymbolAddress((void**)&wall_h, g_wall_h); cudaGetSymbolAddress((void**)&wall_l, g_wall_l);
    cudaGetSymbolAddress((void**)&wrest_h, g_wrest_h); cudaGetSymbolAddress((void**)&wrest_l, g_wrest_l);
    cudaGetSymbolAddress((void**)&qu_h, g_qu_h);   cudaGetSymbolAddress((void**)&qu_l, g_qu_l);
    cudaGetSymbolAddress((void**)&qv_h, g_qv_h);   cudaGetSymbolAddress((void**)&qv_l, g_qv_l);
    cudaGetSymbolAddress((void**)&kl_h, g_kl_h);   cudaGetSymbolAddress((void**)&kl_l, g_kl_l);
    cudaGetSymbolAddress((void**)&khat_h, g_khat_h); cudaGetSymbolAddress((void**)&khat_l, g_khat_l);
    cudaGetSymbolAddress((void**)&cb_h, g_cb_h);   cudaGetSymbolAddress((void**)&cb_l, g_cb_l);
    cudaGetSymbolAddress((void**)&xlr_h, g_xlr_h); cudaGetSymbolAddress((void**)&xlr_l, g_xlr_l);
    cudaGetSymbolAddress((void**)&vt_h, g_vt_h);   cudaGetSymbolAddress((void**)&vt_l, g_vt_l);
    cudaGetSymbolAddress((void**)&wvg_h, g_wvg_h); cudaGetSymbolAddress((void**)&wvg_l, g_wvg_l);

    cudaFuncSetAttribute(attn_kernel, cudaFuncAttributeMaxDynamicSharedMemorySize, SMEM_ATTN);

    // 0. fused preprocessing
    prep_kernel<<<PREP_GRID, 256>>>(W_q, W_kvg, W_res, xl_k_hat, codebook, xl_r, input,
                                    wall_h, wall_l, wrest_h, wrest_l,
                                    khat_h, khat_l, cb_h, cb_l, xlr_h, xlr_l,
                                    xt_h, xt_l, csq, zpk, ctr);

    // 1. fused projection GEMM (Wq | Wkvg), N=4096
    mma_gemm4_kernel<<<dim3(32, 32, 1), 256>>>(xt_h, xt_l, wall_h, wall_l,
                                               proj, 4096, 1024, 1024);

    // 2. per-head LN, biases, silu
    transform_kernel<<<NROWS * CH / 8, 256>>>(proj, x_u, x_v,
                                              qu_h, qu_l, qv_h, qv_l, kl_h, kl_l, vv, gate);

    // 3. V gather-transpose (wide-store variant)
    vt_kernel<<<dim3(SCW / 64, CDV / 32, NBH), 256>>>(xl_v, vv, agg_upper, vt_h, vt_l);

    // 4. merged VQ argmin + BD GEMM (homogeneous footprints)
    vqbd_kernel<<<VB_END, 256>>>(kl_h, kl_l, qv_h, qv_l, cb_h, cb_l, xlr_h, xlr_l,
                                 csq, zpk, rbd);

    // 5. fused attention (persistent work-stealing, heavy-first)
    attn_kernel<<<ATTN_GRID, 256, SMEM_ATTN>>>(qu_h, qu_l, khat_h, khat_l,
                                               cb_h, cb_l, vt_h, vt_l, zpk,
                                               rbd, agg_lower, gate, ctr, wvg_h, wvg_l);

    // 6. output projection
    mma_gemm4_kernel<<<dim3(8, 32, 1), 256>>>(wvg_h, wvg_l, wrest_h, wrest_l,
                                              out, 1024, 1024, 1024);
}

// round 14
// speedup vs baseline: 1.1535x; 1.0447x over previous
#include <cuda_runtime.h>
#include <cuda_bf16.h>
#include <cstdint>

// ---------------------------------------------------------------------------
// Problem constants
// ---------------------------------------------------------------------------
#define CB   8
#define CL   512
#define CM   512
#define CH   8
#define CDK  128
#define CDV  128
#define CS   512
#define CDM  1024
#define CW   1024   // W_REC
#define NBH  64
#define NROWS 4096
#define SCW  1536   // W + S

static __device__ __constant__ const float TAUI = 0.08838834764831845f; // 1/sqrt(128)

typedef __nv_bfloat16 bf16;

// ---------------------------------------------------------------------------
// Scratch
// ---------------------------------------------------------------------------
__device__ float g_proj  [(size_t)NROWS * 4096];   // qraw | k | v | g
__device__ float g_gate  [(size_t)NROWS * CDM];
__device__ float g_rbd   [(size_t)NBH * CL * CW];
__device__ unsigned long long g_zpk[NBH * CL];
__device__ float g_csq   [CH * CS];
__device__ float g_cbias [NBH * CS];
__device__ int   g_unit_ctr;

__device__ bf16 g_xt_h   [(size_t)NROWS * CDM];
__device__ bf16 g_xt_l   [(size_t)NROWS * CDM];
__device__ bf16 g_wall_h [(size_t)4096 * 1024];   // Wq^T | Wkvg^T
__device__ bf16 g_wall_l [(size_t)4096 * 1024];
__device__ bf16 g_wrest_h[(size_t)1024 * 1024];
__device__ bf16 g_wrest_l[(size_t)1024 * 1024];
__device__ bf16 g_qu_h   [(size_t)NBH * CL * CDK];
__device__ bf16 g_qu_l   [(size_t)NBH * CL * CDK];
__device__ bf16 g_qv_h   [(size_t)NBH * CL * CDK];
__device__ bf16 g_qv_l   [(size_t)NBH * CL * CDK];
__device__ bf16 g_kl_h   [(size_t)NBH * CL * CDK];
__device__ bf16 g_kl_l   [(size_t)NBH * CL * CDK];
__device__ bf16 g_khat_h [(size_t)NBH * CM * CDK];
__device__ bf16 g_khat_l [(size_t)NBH * CM * CDK];
__device__ bf16 g_cb_h   [(size_t)CH * CS * CDK];
__device__ bf16 g_cb_l   [(size_t)CH * CS * CDK];
__device__ bf16 g_xlr_h  [(size_t)CH * CW * CDK];
__device__ bf16 g_xlr_l  [(size_t)CH * CW * CDK];
__device__ bf16 g_xlv_h  [(size_t)NBH * CM * CDV];   // xl_v bf16 (w-major)
__device__ bf16 g_xlv_l  [(size_t)NBH * CM * CDV];
__device__ bf16 g_agu_h  [(size_t)NBH * CS * CDV];   // agg_upper bf16 (w-major)
__device__ bf16 g_agu_l  [(size_t)NBH * CS * CDV];
__device__ bf16 g_vvh    [(size_t)NBH * CL * CDV];   // current v bf16 (w-major)
__device__ bf16 g_vvl    [(size_t)NBH * CL * CDV];
__device__ bf16 g_wvg_h  [(size_t)NROWS * CDM];
__device__ bf16 g_wvg_l  [(size_t)NROWS * CDM];

// ---------------------------------------------------------------------------
// primitives
// ---------------------------------------------------------------------------
__device__ __forceinline__ uint32_t cvta_s(const void* p) {
    return (uint32_t)__cvta_generic_to_shared(p);
}
__device__ __forceinline__ void ldmx4(uint32_t addr, uint32_t& r0, uint32_t& r1,
                                      uint32_t& r2, uint32_t& r3) {
    asm volatile("ldmatrix.sync.aligned.m8n8.x4.shared.b16 {%0,%1,%2,%3}, [%4];"
                 : "=r"(r0), "=r"(r1), "=r"(r2), "=r"(r3) : "r"(addr));
}
__device__ __forceinline__ void ldmx4t(uint32_t addr, uint32_t& r0, uint32_t& r1,
                                       uint32_t& r2, uint32_t& r3) {
    asm volatile("ldmatrix.sync.aligned.m8n8.x4.trans.shared.b16 {%0,%1,%2,%3}, [%4];"
                 : "=r"(r0), "=r"(r1), "=r"(r2), "=r"(r3) : "r"(addr));
}
__device__ __forceinline__ void mma16816(float c[4], const uint32_t a[4], const uint32_t b[2]) {
    asm volatile(
        "mma.sync.aligned.m16n8k16.row.col.f32.bf16.bf16.f32 "
        "{%0,%1,%2,%3}, {%4,%5,%6,%7}, {%8,%9}, {%0,%1,%2,%3};"
        : "+f"(c[0]), "+f"(c[1]), "+f"(c[2]), "+f"(c[3])
        : "r"(a[0]), "r"(a[1]), "r"(a[2]), "r"(a[3]), "r"(b[0]), "r"(b[1]));
}
__device__ __forceinline__ void cpa16(uint32_t d, const void* s) {
    asm volatile("cp.async.ca.shared.global [%0], [%1], 16;" :: "r"(d), "l"(s));
}
__device__ __forceinline__ void cpa_commit() {
    asm volatile("cp.async.commit_group;");
}
template <int NN>
__device__ __forceinline__ void cpa_wait() {
    asm volatile("cp.async.wait_group %0;" :: "n"(NN));
}

__device__ __forceinline__ void splitw(float x, bf16* h, bf16* l) {
    bf16 hh = __float2bfloat16_rn(x);
    *h = hh;
    *l = __float2bfloat16_rn(x - __bfloat162float(hh));
}
__device__ __forceinline__ void split4(float4 v, bf16* hp, bf16* lp) {
    __nv_bfloat162 h0 = __floats2bfloat162_rn(v.x, v.y);
    __nv_bfloat162 h1 = __floats2bfloat162_rn(v.z, v.w);
    float2 f0 = __bfloat1622float2(h0);
    float2 f1 = __bfloat1622float2(h1);
    __nv_bfloat162 l0 = __floats2bfloat162_rn(v.x - f0.x, v.y - f0.y);
    __nv_bfloat162 l1 = __floats2bfloat162_rn(v.z - f1.x, v.w - f1.y);
    uint2 hv, lv;
    hv.x = *(uint32_t*)&h0; hv.y = *(uint32_t*)&h1;
    lv.x = *(uint32_t*)&l0; lv.y = *(uint32_t*)&l1;
    *(uint2*)hp = hv;
    *(uint2*)lp = lv;
}
__device__ __forceinline__ uint32_t packbf(float x, float y) {
    __nv_bfloat162 t = __floats2bfloat162_rn(x, y);
    return *(uint32_t*)&t;
}
__device__ __forceinline__ uint32_t packbf_res(float x, float y, uint32_t hp) {
    __nv_bfloat162 hv = *(__nv_bfloat162*)&hp;
    float2 f = __bfloat1622float2(hv);
    return packbf(x - f.x, y - f.y);
}

// ---------------------------------------------------------------------------
// reductions
// ---------------------------------------------------------------------------
__device__ __forceinline__ float block_sum(float v) {
    __shared__ float sb_[8];
    int tid = threadIdx.x;
    int nw  = blockDim.x >> 5;
    #pragma unroll
    for (int o = 16; o; o >>= 1) v += __shfl_down_sync(0xffffffffu, v, o);
    __syncthreads();
    if ((tid & 31) == 0) sb_[tid >> 5] = v;
    __syncthreads();
    float r = 0.f;
    for (int i = 0; i < nw; ++i) r += sb_[i];
    return r;
}
__device__ __forceinline__ float warp_sum(float v) {
    #pragma unroll
    for (int o = 16; o; o >>= 1) v += __shfl_xor_sync(0xffffffffu, v, o);
    return v;
}

// ---------------------------------------------------------------------------
// Fused preprocessing (one launch, all light blocks)
// ---------------------------------------------------------------------------
#define PS0 1024                  // Wq transpose
#define PS1 (PS0 + 3072)          // Wkvg transpose
#define PS2 (PS1 + 1024)          // Wres transpose
#define PS3 (PS2 + 4096)          // khat convert
#define PS4 (PS3 + 512)           // cb convert
#define PS5 (PS4 + 1024)          // xlr convert
#define PS5b (PS5 + 4096)         // xl_v convert
#define PS5c (PS5b + 4096)        // agg_upper convert
#define PS6 (PS5c + 4096)         // LN rows
#define PS7 (PS6 + 512)           // csq
#define PS7b (PS7 + 32)           // cache bias table
#define PS8 (PS7b + 32)           // zinit
#define PREP_GRID PS8

__device__ __forceinline__ void do_transpose(const float* __restrict__ src,
                                             bf16* __restrict__ dh,
                                             bf16* __restrict__ dl,
                                             int R, int C, int id,
                                             float (*tile)[33]) {
    int bx = id % (C >> 5), by = id / (C >> 5);
    int c0 = bx * 32, r0 = by * 32;
    int x = threadIdx.x & 31, y = (threadIdx.x >> 5) * 4;
    #pragma unroll
    for (int i = 0; i < 4; ++i)
        tile[y + i][x] = src[(size_t)(r0 + y + i) * C + c0 + x];
    __syncthreads();
    #pragma unroll
    for (int i = 0; i < 4; ++i) {
        size_t o = (size_t)(c0 + y + i) * R + r0 + x;
        splitw(tile[x][y + i], dh + o, dl + o);
    }
}
__device__ __forceinline__ void do_convert(const float* __restrict__ src,
                                           bf16* __restrict__ h,
                                           bf16* __restrict__ l, int id) {
    size_t idx = (size_t)id * 256 + threadIdx.x;
    float4 v = ((const float4*)src)[idx];
    split4(v, h + idx * 4, l + idx * 4);
}

__global__ void __launch_bounds__(256) prep_kernel(
    const float* __restrict__ W_q, const float* __restrict__ W_kvg,
    const float* __restrict__ W_res,
    const float* __restrict__ xl_k_hat, const float* __restrict__ codebook,
    const float* __restrict__ xl_r, const float* __restrict__ input,
    const float* __restrict__ xl_v, const float* __restrict__ agg_upper,
    const float* __restrict__ agg_lower,
    bf16* wall_h, bf16* wall_l, bf16* wrest_h, bf16* wrest_l,
    bf16* khat_h, bf16* khat_l, bf16* cb_h, bf16* cb_l,
    bf16* xlr_h, bf16* xlr_l, bf16* xlv_h, bf16* xlv_l,
    bf16* agu_h, bf16* agu_l, bf16* xt_h, bf16* xt_l,
    float* csq, float* cbias, unsigned long long* zpk, int* ctr) {

    __shared__ float tile[32][33];
    int bid = blockIdx.x;
    int tid = threadIdx.x;

    if (bid < PS0) {
        do_transpose(W_q, wall_h, wall_l, 1024, 1024, bid, tile);
    } else if (bid < PS1) {
        do_transpose(W_kvg, wall_h + (size_t)1024 * 1024, wall_l + (size_t)1024 * 1024,
                     1024, 3072, bid - PS0, tile);
    } else if (bid < PS2) {
        do_transpose(W_res, wrest_h, wrest_l, 1024, 1024, bid - PS1, tile);
    } else if (bid < PS3) {
        do_convert(xl_k_hat, khat_h, khat_l, bid - PS2);
    } else if (bid < PS4) {
        do_convert(codebook, cb_h, cb_l, bid - PS3);
    } else if (bid < PS5) {
        do_convert(xl_r, xlr_h, xlr_l, bid - PS4);
    } else if (bid < PS5b) {
        do_convert(xl_v, xlv_h, xlv_l, bid - PS5);
    } else if (bid < PS5c) {
        do_convert(agg_upper, agu_h, agu_l, bid - PS5b);
    } else if (bid < PS6) {
        int row = bid - PS5c;
        const float* xr = input + (size_t)row * CDM;
        float4 v = *(const float4*)(xr + tid * 4);
        float s = v.x + v.y + v.z + v.w;
        float mu = block_sum(s) * (1.f / 1024.f);
        v.x -= mu; v.y -= mu; v.z -= mu; v.w -= mu;
        float s2 = v.x * v.x + v.y * v.y + v.z * v.z + v.w * v.w;
        float rstd = rsqrtf(block_sum(s2) * (1.f / 1024.f) + 1e-6f);
        v.x *= rstd; v.y *= rstd; v.z *= rstd; v.w *= rstd;
        split4(v, xt_h + (size_t)row * CDM + tid * 4, xt_l + (size_t)row * CDM + tid * 4);
    } else if (bid < PS7) {
        int wid  = tid >> 5, lane = tid & 31;
        int row = (bid - PS6) * 8 + wid;
        float4 v = *(const float4*)(codebook + (size_t)row * CDK + lane * 4);
        float s = warp_sum(v.x * v.x + v.y * v.y + v.z * v.z + v.w * v.w);
        if (lane == 0) csq[row] = s;
    } else if (bid < PS7b) {
        size_t idx = (size_t)(bid - PS7) * 256 + tid;   // 32*256*4 = 32768 floats
        float4 a = ((const float4*)agg_lower)[idx];
        float4 bv;
        bv.x = (a.x > 0.f) ? logf(fmaxf(a.x, 1e-30f)) : -1e30f;
        bv.y = (a.y > 0.f) ? logf(fmaxf(a.y, 1e-30f)) : -1e30f;
        bv.z = (a.z > 0.f) ? logf(fmaxf(a.z, 1e-30f)) : -1e30f;
        bv.w = (a.w > 0.f) ? logf(fmaxf(a.w, 1e-30f)) : -1e30f;
        ((float4*)cbias)[idx] = bv;
    } else {
        int id = bid - PS7b;
        size_t base = (size_t)id * 1024 + tid * 4;
        zpk[base + 0] = ~0ull; zpk[base + 1] = ~0ull;
        zpk[base + 2] = ~0ull; zpk[base + 3] = ~0ull;
        if (id == 0 && tid == 0) *ctr = 0;
    }
}

// ---------------------------------------------------------------------------
// per-(b,l,h) transform (reads fused proj buffer; emits vv as bf16 hi/lo)
// ---------------------------------------------------------------------------
__global__ void __launch_bounds__(256) transform_kernel(const float* __restrict__ proj,
                                                        const float* __restrict__ x_u,
                                                        const float* __restrict__ x_v,
                                                        bf16* __restrict__ quh, bf16* __restrict__ qul,
                                                        bf16* __restrict__ qvh, bf16* __restrict__ qvl,
                                                        bf16* __restrict__ klh, bf16* __restrict__ kll,
                                                        bf16* __restrict__ vvh, bf16* __restrict__ vvl,
                                                        float* __restrict__ gate) {
    int wid  = threadIdx.x >> 5;
    int lane = threadIdx.x & 31;
    int idx = blockIdx.x * 8 + wid;
    int h  = idx & 7;
    int bl = idx >> 3;
    int b = bl >> 9, l = bl & 511;
    int d0 = lane * 4;
    const float* prow = proj + (size_t)bl * 4096 + h * CDK + d0;

    float4 q = *(const float4*)(prow);
    float mu = warp_sum(q.x + q.y + q.z + q.w) * (1.f / 128.f);
    q.x -= mu; q.y -= mu; q.z -= mu; q.w -= mu;
    float var = warp_sum(q.x * q.x + q.y * q.y + q.z * q.z + q.w * q.w) * (1.f / 128.f);
    float rs = rsqrtf(var + 1e-6f);
    float4 xu = *(const float4*)(x_u + h * CDK + d0);
    float4 xv = *(const float4*)(x_v + h * CDK + d0);
    size_t o = (((size_t)b * CH + h) * CL + l) * CDK + d0;
    split4(make_float4(q.x * rs + xu.x, q.y * rs + xu.y, q.z * rs + xu.z, q.w * rs + xu.w),
           quh + o, qul + o);
    split4(make_float4(q.x * rs + xv.x, q.y * rs + xv.y, q.z * rs + xv.z, q.w * rs + xv.w),
           qvh + o, qvl + o);

    float4 k = *(const float4*)(prow + 1024);
    float kmu = warp_sum(k.x + k.y + k.z + k.w) * (1.f / 128.f);
    k.x -= kmu; k.y -= kmu; k.z -= kmu; k.w -= kmu;
    float kvar = warp_sum(k.x * k.x + k.y * k.y + k.z * k.z + k.w * k.w) * (1.f / 128.f);
    float krs = rsqrtf(kvar + 1e-6f);
    split4(make_float4(k.x * krs, k.y * krs, k.z * krs, k.w * krs), klh + o, kll + o);

    split4(*(const float4*)(prow + 2048), vvh + o, vvl + o);

    float4 gg = *(const float4*)(prow + 3072);
    float4 gs;
    gs.x = gg.x / (1.f + __expf(-gg.x));
    gs.y = gg.y / (1.f + __expf(-gg.y));
    gs.z = gg.z / (1.f + __expf(-gg.z));
    gs.w = gg.w / (1.f + __expf(-gg.w));
    *(float4*)(gate + (size_t)bl * CDM + h * CDK + d0) = gs;
}

// ---------------------------------------------------------------------------
// NT tensor-core GEMM body (bf16x3, 3-stage cp.async). MODE: 0=BD, 3=VQ, 4=PROJ
// ---------------------------------------------------------------------------
#define STG_B 12288
#define CMP_B 6144
#define SBOFF 36864
template <int MODE>
__device__ __forceinline__ void gemm_body(
    char* smem, int bm, int bn, int bh,
    const bf16* __restrict__ Ah, const bf16* __restrict__ Al,
    const bf16* __restrict__ Bh, const bf16* __restrict__ Bl,
    const float* __restrict__ csq,
    unsigned long long* zpk_out,
    float* __restrict__ outp,
    int N, int K, int lda) {

    int tid  = threadIdx.x;
    int lane = tid & 31, warp = tid >> 5;
    int wm = warp >> 2, wn = warp & 3;
    int h  = bh & 7;

    if (MODE == 0 && (bn + bm) < 257) return;   // BD dead tiles

    size_t aoff = (MODE == 4) ? 0 : (size_t)bh * CL * CDK;

    int srow = tid >> 1;
    int sc8  = (tid & 1) * 8;
    const bf16* a_h = Ah + aoff + (size_t)(bm + srow) * lda + sc8;
    const bf16* a_l = Al + aoff + (size_t)(bm + srow) * lda + sc8;
    const bf16 *b_h, *b_l;
    {
        int n = bn + srow;
        size_t boff;
        if (MODE == 0)      boff = ((size_t)h * CW + n) * CDK;
        else if (MODE == 3) boff = ((size_t)h * CS + n) * CDK;
        else                boff = (size_t)n * K;
        b_h = Bh + boff + sc8; b_l = Bl + boff + sc8;
    }

    uint32_t sA = cvta_s(smem);
    uint32_t sB = sA + SBOFF;
    uint32_t dA = sA + (uint32_t)(srow * 24 + sc8) * 2;
    uint32_t dB = sB + (uint32_t)(srow * 24 + sc8) * 2;

    int a_off = (wm * 64 + (lane & 15)) * 24 + ((lane >> 4) << 3);
    int b_off = (wn * 32 + ((lane >> 4) << 3) + (lane & 7)) * 24 + (((lane >> 3) & 1) << 3);

    float acc[4][4][4] = {};
    int T = K >> 4;

    cpa16(dA,         a_h);  cpa16(dA + CMP_B, a_l);
    cpa16(dB,         b_h);  cpa16(dB + CMP_B, b_l);
    cpa_commit();

    #pragma unroll 1
    for (int kt = 0; kt < T; ++kt) {
        if (kt + 1 < T) {
            int st = (kt + 1) % 3;
            int k0 = (kt + 1) * 16;
            cpa16(dA + st * STG_B,         a_h + k0);
            cpa16(dA + st * STG_B + CMP_B, a_l + k0);
            cpa16(dB + st * STG_B,         b_h + k0);
            cpa16(dB + st * STG_B + CMP_B, b_l + k0);
            cpa_commit();
            cpa_wait<1>();
        } else {
            cpa_wait<0>();
        }
        __syncthreads();

        int cs = kt % 3;
        uint32_t aH = sA + cs * STG_B + (uint32_t)a_off * 2;
        uint32_t bH = sB + cs * STG_B + (uint32_t)b_off * 2;
        uint32_t ah[4][4], al[4][4], bhf[4][2], blf[4][2];
        #pragma unroll
        for (int t = 0; t < 4; ++t) {
            ldmx4(aH + t * 768,         ah[t][0], ah[t][1], ah[t][2], ah[t][3]);
            ldmx4(aH + CMP_B + t * 768, al[t][0], al[t][1], al[t][2], al[t][3]);
        }
        #pragma unroll
        for (int u2 = 0; u2 < 2; ++u2) {
            uint32_t r0, r1, r2, r3;
            ldmx4(bH + u2 * 768, r0, r1, r2, r3);
            bhf[2 * u2][0] = r0; bhf[2 * u2][1] = r1;
            bhf[2 * u2 + 1][0] = r2; bhf[2 * u2 + 1][1] = r3;
            ldmx4(bH + CMP_B + u2 * 768, r0, r1, r2, r3);
            blf[2 * u2][0] = r0; blf[2 * u2][1] = r1;
            blf[2 * u2 + 1][0] = r2; blf[2 * u2 + 1][1] = r3;
        }
        #pragma unroll
        for (int t = 0; t < 4; ++t)
            #pragma unroll
            for (int u = 0; u < 4; ++u) {
                mma16816(acc[t][u], ah[t], bhf[u]);
                mma16816(acc[t][u], ah[t], blf[u]);
                mma16816(acc[t][u], al[t], bhf[u]);
            }
    }

    int g  = lane >> 2;
    int qd = lane & 3;

    if constexpr (MODE == 4) {
        #pragma unroll
        for (int t = 0; t < 4; ++t) {
            int r = bm + wm * 64 + t * 16 + g;
            #pragma unroll
            for (int u = 0; u < 4; ++u) {
                int c = bn + wn * 32 + u * 8 + qd * 2;
                *(float2*)(outp + (size_t)r * N + c) =
                    make_float2(acc[t][u][0], acc[t][u][1]);
                *(float2*)(outp + (size_t)(r + 8) * N + c) =
                    make_float2(acc[t][u][2], acc[t][u][3]);
            }
        }
    } else if constexpr (MODE == 0) {
        #pragma unroll
        for (int t = 0; t < 4; ++t) {
            int l = bm + wm * 64 + t * 16 + g;
            #pragma unroll
            for (int u = 0; u < 4; ++u) {
                int c = bn + wn * 32 + u * 8 + qd * 2;
                *(float2*)(outp + ((size_t)bh * CL + l) * CW + c) =
                    make_float2(acc[t][u][0] * TAUI, acc[t][u][1] * TAUI);
                *(float2*)(outp + ((size_t)bh * CL + l + 8) * CW + c) =
                    make_float2(acc[t][u][2] * TAUI, acc[t][u][3] * TAUI);
            }
        }
    } else {   // VQ argmin
        unsigned long long* zmin = reinterpret_cast<unsigned long long*>(smem);
        __syncthreads();
        if (tid < 128) zmin[tid] = ~0ull;
        __syncthreads();
        #pragma unroll
        for (int t = 0; t < 4; ++t) {
            unsigned long long b0 = ~0ull, b1 = ~0ull;
            #pragma unroll
            for (int u = 0; u < 4; ++u) {
                #pragma unroll
                for (int p = 0; p < 2; ++p) {
                    int s = bn + wn * 32 + u * 8 + qd * 2 + p;
                    float cs = csq[h * CS + s];
                    {
                        float val = cs - 2.f * acc[t][u][p];
                        unsigned uu = __float_as_uint(val);
                        uu = (uu & 0x80000000u) ? ~uu : (uu | 0x80000000u);
                        unsigned long long key = ((unsigned long long)uu << 32) | (unsigned)s;
                        if (key < b0) b0 = key;
                    }
                    {
                        float val = cs - 2.f * acc[t][u][2 + p];
                        unsigned uu = __float_as_uint(val);
                        uu = (uu & 0x80000000u) ? ~uu : (uu | 0x80000000u);
                        unsigned long long key = ((unsigned long long)uu << 32) | (unsigned)s;
                        if (key < b1) b1 = key;
                    }
                }
            }
            unsigned long long o;
            o = __shfl_xor_sync(0xffffffffu, b0, 1); if (o < b0) b0 = o;
            o = __shfl_xor_sync(0xffffffffu, b0, 2); if (o < b0) b0 = o;
            o = __shfl_xor_sync(0xffffffffu, b1, 1); if (o < b1) b1 = o;
            o = __shfl_xor_sync(0xffffffffu, b1, 2); if (o < b1) b1 = o;
            if (qd == 0) {
                atomicMin(&zmin[wm * 64 + t * 16 + g], b0);
                atomicMin(&zmin[wm * 64 + t * 16 + g + 8], b1);
            }
        }
        __syncthreads();
        if (tid < 128)
            atomicMin(&zpk_out[(size_t)bh * CL + bm + tid], zmin[tid]);
    }
}

// wrapper kernels
__global__ void __launch_bounds__(256) mma_gemm4_kernel(
    const bf16* __restrict__ Ah, const bf16* __restrict__ Al,
    const bf16* __restrict__ Bh, const bf16* __restrict__ Bl,
    float* __restrict__ outp, int N, int K, int lda) {
    __shared__ __align__(16) char smem[73728];
    gemm_body<4>(smem, blockIdx.y * 128, blockIdx.x * 128, 0,
                 Ah, Al, Bh, Bl, nullptr, nullptr, outp, N, K, lda);
}

// merged VQ + BD (footprint-homogeneous GEMM blocks)
#define VB_VQ 1024
#define VB_END 3072
__global__ void __launch_bounds__(256) vqbd_kernel(
    const bf16* __restrict__ kl_h, const bf16* __restrict__ kl_l,
    const bf16* __restrict__ qv_h, const bf16* __restrict__ qv_l,
    const bf16* __restrict__ cb_h, const bf16* __restrict__ cb_l,
    const bf16* __restrict__ xlr_h, const bf16* __restrict__ xlr_l,
    const float* __restrict__ csq, unsigned long long* zpk,
    float* __restrict__ rbd) {
    __shared__ __align__(16) char smem[73728];
    int bid = blockIdx.x;
    if (bid < VB_VQ) {
        int x = bid & 3, y = (bid >> 2) & 3, z = bid >> 4;
        gemm_body<3>(smem, y * 128, x * 128, z, kl_h, kl_l, cb_h, cb_l,
                     csq, zpk, nullptr, 512, 128, 128);
    } else {
        int id = bid - VB_VQ;
        int x = id & 7, y = (id >> 3) & 3, z = id >> 5;
        gemm_body<0>(smem, y * 128, x * 128, z, qv_h, qv_l, xlr_h, xlr_l,
                     nullptr, nullptr, rbd, 1024, 128, 128);
    }
}

// ---------------------------------------------------------------------------
// Fused attention (persistent, work-stealing, heavy-first).
// V loaded w-major straight from sources; B fragments via ldmatrix.trans.
// ---------------------------------------------------------------------------
#define APITCH 272
#define APLANE 34816
#define ABUF   69632
#define NUNITS 256
__global__ void __launch_bounds__(256) attn_kernel(
    const bf16* __restrict__ quh, const bf16* __restrict__ qul,
    const bf16* __restrict__ khat_h, const bf16* __restrict__ khat_l,
    const bf16* __restrict__ cb_h, const bf16* __restrict__ cb_l,
    const bf16* __restrict__ xlv_h, const bf16* __restrict__ xlv_l,
    const bf16* __restrict__ vvh, const bf16* __restrict__ vvl,
    const bf16* __restrict__ agu_h, const bf16* __restrict__ agu_l,
    const unsigned long long* __restrict__ zpk,
    const float* __restrict__ rbd,
    const float* __restrict__ cbias,
    const float* __restrict__ gate,
    int* __restrict__ unit_ctr,
    bf16* __restrict__ outh, bf16* __restrict__ outl) {

    extern __shared__ __align__(16) char smem_raw[];
    uint32_t sQU = cvta_s(smem_raw);
    uint32_t sKT = sQU + ABUF;
    uint32_t sVT = sQU + 2 * ABUF;
    __shared__ int s_unit;

    int tid  = threadIdx.x;
    int lane = tid & 31, warp = tid >> 5;
    int g = lane >> 2, qd = lane & 3;

    for (;;) {
        __syncthreads();
        if (tid == 0) s_unit = atomicAdd(unit_ctr, 1);
        __syncthreads();
        int unit = s_unit;
        if (unit >= NUNITS) break;

        int bm = (3 - (unit >> 6)) * 128;    // heavy units first
        int bh = unit & 63;
        int h  = bh & 7;
        int b  = bh >> 3;

        int tiles[12]; int nt = 0;
        #pragma unroll
        for (int j = 0; j < 12; ++j)
            if (!(j < 8 && j * 128 >= bm + CM + 128)) tiles[nt++] = j;

        auto load_qu = [&]() {
            size_t qoff = (size_t)bh * CL * CDK;
            #pragma unroll
            for (int i = 0; i < 8; ++i) {
                int id = tid + i * 256;
                int r = id >> 4, c = id & 15;
                uint32_t d = sQU + r * APITCH + c * 16;
                cpa16(d,          quh + qoff + (size_t)(bm + r) * CDK + c * 8);
                cpa16(d + APLANE, qul + qoff + (size_t)(bm + r) * CDK + c * 8);
            }
        };
        auto load_kt = [&](int j) {
            #pragma unroll
            for (int i = 0; i < 8; ++i) {
                int id = tid + i * 256;
                int r = id >> 4, c = id & 15;
                int n = j * 128 + r;
                const bf16 *sh, *sl;
                if (j < 4) {
                    size_t o = ((size_t)bh * CM + n) * CDK;
                    sh = khat_h + o; sl = khat_l + o;
                } else if (j < 8) {
                    unsigned zi = (unsigned)(zpk[(size_t)bh * CL + (n - CM)] & 0xffffffffull);
                    size_t o = ((size_t)h * CS + zi) * CDK;
                    sh = cb_h + o; sl = cb_l + o;
                } else {
                    size_t o = ((size_t)h * CS + (n - CW)) * CDK;
                    sh = cb_h + o; sl = cb_l + o;
                }
                uint32_t d = sKT + r * APITCH + c * 16;
                cpa16(d,          sh + c * 8);
                cpa16(d + APLANE, sl + c * 8);
            }
        };
        // V tile: w-major rows (128 w x 128 v), straight gather
        auto load_vt = [&](int j) {
            #pragma unroll
            for (int i = 0; i < 8; ++i) {
                int id = tid + i * 256;
                int r = id >> 4, c = id & 15;
                int w = j * 128 + r;
                const bf16 *sh, *sl;
                if (j < 4) {
                    size_t o = ((size_t)bh * CM + w) * CDV;
                    sh = xlv_h + o; sl = xlv_l + o;
                } else if (j < 8) {
                    size_t o = ((size_t)bh * CL + (w - CM)) * CDV;
                    sh = vvh + o; sl = vvl + o;
                } else {
                    size_t o = ((size_t)bh * CS + (w - CW)) * CDV;
                    sh = agu_h + o; sl = agu_l + o;
                }
                uint32_t d = sVT + r * APITCH + c * 16;
                cpa16(d,          sh + c * 8);
                cpa16(d + APLANE, sl + c * 8);
            }
        };

        uint32_t quB = sQU + (uint32_t)(warp * 16 + (lane & 15)) * APITCH + ((lane >> 4) << 4);
        uint32_t bB  = (uint32_t)((((lane >> 4) << 3) + (lane & 7)) * APITCH) + (((lane >> 3) & 1) << 4);
        // trans-load base for w-major V: rows = k(w), byte-cols = n(v)
        uint32_t tB  = (uint32_t)(((lane & 7) + ((lane >> 3) & 1) * 8) * APITCH) + (((lane >> 4) << 3) << 1);

        int l0 = bm + warp * 16 + g;
        int l1 = l0 + 8;

        float O[16][4] = {};
        float m0 = -3.4e38f, m1 = -3.4e38f, d0 = 0.f, d1 = 0.f;

        load_qu();
        load_kt(tiles[0]);
        cpa_commit();

        #pragma unroll 1
        for (int ti = 0; ti < nt; ++ti) {
            int j = tiles[ti];
            cpa_wait<0>();
            __syncthreads();
            load_vt(j);
            cpa_commit();

            float S[16][4] = {};
            #pragma unroll
            for (int kg = 0; kg < 8; ++kg) {
                uint32_t ah[4], al[4];
                ldmx4(quB + kg * 32,          ah[0], ah[1], ah[2], ah[3]);
                ldmx4(quB + APLANE + kg * 32, al[0], al[1], al[2], al[3]);
                #pragma unroll
                for (int nf = 0; nf < 8; ++nf) {
                    uint32_t base = sKT + bB + nf * (16 * APITCH) + kg * 32;
                    uint32_t p0, p1, p2, p3, q0, q1, q2, q3;
                    ldmx4(base,          p0, p1, p2, p3);
                    ldmx4(base + APLANE, q0, q1, q2, q3);
                    uint32_t bp[2], bq[2];
                    bp[0] = p0; bp[1] = p1; bq[0] = q0; bq[1] = q1;
                    mma16816(S[nf * 2], ah, bp);
                    mma16816(S[nf * 2], ah, bq);
                    mma16816(S[nf * 2], al, bp);
                    bp[0] = p2; bp[1] = p3; bq[0] = q2; bq[1] = q3;
                    mma16816(S[nf * 2 + 1], ah, bp);
                    mma16816(S[nf * 2 + 1], ah, bq);
                    mma16816(S[nf * 2 + 1], al, bp);
                }
            }

            if (j < 8) {
                const float* rr0 = rbd + ((size_t)bh * CL + l0) * CW + (CL - 1) - l0;
                const float* rr1 = rbd + ((size_t)bh * CL + l1) * CW + (CL - 1) - l1;
                int wb = j * 128 + qd * 2;
                #pragma unroll
                for (int u = 0; u < 16; ++u) {
                    int w = wb + u * 8;
                    S[u][0] = (w     <= l0 + CM) ? S[u][0] * TAUI + rr0[w]     : -1e30f;
                    S[u][1] = (w + 1 <= l0 + CM) ? S[u][1] * TAUI + rr0[w + 1] : -1e30f;
                    S[u][2] = (w     <= l1 + CM) ? S[u][2] * TAUI + rr1[w]     : -1e30f;
                    S[u][3] = (w + 1 <= l1 + CM) ? S[u][3] * TAUI + rr1[w + 1] : -1e30f;
                }
            } else {
                int sb = (j - 8) * 128 + qd * 2;
                const float* cb = cbias + (size_t)bh * CS;
                #pragma unroll
                for (int u = 0; u < 16; ++u) {
                    int s = sb + u * 8;
                    float b0 = cb[s];
                    float b1 = cb[s + 1];
                    S[u][0] = S[u][0] * TAUI + b0;
                    S[u][1] = S[u][1] * TAUI + b1;
                    S[u][2] = S[u][2] * TAUI + b0;
                    S[u][3] = S[u][3] * TAUI + b1;
                }
            }

            float mx0 = -3.4e38f, mx1 = -3.4e38f;
            #pragma unroll
            for (int u = 0; u < 16; ++u) {
                mx0 = fmaxf(mx0, fmaxf(S[u][0], S[u][1]));
                mx1 = fmaxf(mx1, fmaxf(S[u][2], S[u][3]));
            }
            mx0 = fmaxf(mx0, __shfl_xor_sync(0xffffffffu, mx0, 1));
            mx0 = fmaxf(mx0, __shfl_xor_sync(0xffffffffu, mx0, 2));
            mx1 = fmaxf(mx1, __shfl_xor_sync(0xffffffffu, mx1, 1));
            mx1 = fmaxf(mx1, __shfl_xor_sync(0xffffffffu, mx1, 2));
            float nm0 = fmaxf(m0, mx0), nm1 = fmaxf(m1, mx1);
            float al0 = __expf(m0 - nm0), al1 = __expf(m1 - nm1);
            m0 = nm0; m1 = nm1;
            float s0 = 0.f, s1 = 0.f;
            #pragma unroll
            for (int u = 0; u < 16; ++u) {
                S[u][0] = __expf(S[u][0] - m0);
                S[u][1] = __expf(S[u][1] - m0);
                S[u][2] = __expf(S[u][2] - m1);
                S[u][3] = __expf(S[u][3] - m1);
                s0 += S[u][0] + S[u][1];
                s1 += S[u][2] + S[u][3];
            }
            s0 += __shfl_xor_sync(0xffffffffu, s0, 1);
            s0 += __shfl_xor_sync(0xffffffffu, s0, 2);
            s1 += __shfl_xor_sync(0xffffffffu, s1, 1);
            s1 += __shfl_xor_sync(0xffffffffu, s1, 2);
            d0 = d0 * al0 + s0;
            d1 = d1 * al1 + s1;
            #pragma unroll
            for (int u = 0; u < 16; ++u) {
                O[u][0] *= al0; O[u][1] *= al0;
                O[u][2] *= al1; O[u][3] *= al1;
            }

            cpa_wait<0>();
            __syncthreads();
            if (ti + 1 < nt) { load_kt(tiles[ti + 1]); cpa_commit(); }

            // O += P @ V  (V w-major; B fragments via ldmatrix.trans)
            #pragma unroll
            for (int kg = 0; kg < 8; ++kg) {
                int u2 = kg * 2;
                uint32_t pah[4], pal[4];
                pah[0] = packbf(S[u2][0], S[u2][1]);
                pah[1] = packbf(S[u2][2], S[u2][3]);
                pah[2] = packbf(S[u2 + 1][0], S[u2 + 1][1]);
                pah[3] = packbf(S[u2 + 1][2], S[u2 + 1][3]);
                pal[0] = packbf_res(S[u2][0], S[u2][1], pah[0]);
                pal[1] = packbf_res(S[u2][2], S[u2][3], pah[1]);
                pal[2] = packbf_res(S[u2 + 1][0], S[u2 + 1][1], pah[2]);
                pal[3] = packbf_res(S[u2 + 1][2], S[u2 + 1][3], pah[3]);
                #pragma unroll
                for (int nf = 0; nf < 8; ++nf) {
                    uint32_t baseT = sVT + tB + nf * 32 + kg * (16 * APITCH);
                    uint32_t p0, p1, p2, p3, q0, q1, q2, q3;
                    ldmx4t(baseT,          p0, p1, p2, p3);
                    ldmx4t(baseT + APLANE, q0, q1, q2, q3);
                    uint32_t bp[2], bq[2];
                    bp[0] = p0; bp[1] = p1; bq[0] = q0; bq[1] = q1;
                    mma16816(O[nf * 2], pah, bp);
                    mma16816(O[nf * 2], pah, bq);
                    mma16816(O[nf * 2], pal, bp);
                    bp[0] = p2; bp[1] = p3; bq[0] = q2; bq[1] = q3;
                    mma16816(O[nf * 2 + 1], pah, bp);
                    mma16816(O[nf * 2 + 1], pah, bq);
                    mma16816(O[nf * 2 + 1], pal, bp);
                }
            }
        }

        float i0 = 1.f / d0, i1 = 1.f / d1;
        #pragma unroll
        for (int u = 0; u < 16; ++u) {
            int c = (u << 3) + qd * 2;
            size_t o0 = ((size_t)b * CL + l0) * CDM + h * CDV + c;
            size_t o1 = ((size_t)b * CL + l1) * CDM + h * CDV + c;
            float2 g0 = *(const float2*)(gate + o0);
            float2 g1 = *(const float2*)(gate + o1);
            splitw(O[u][0] * i0 * g0.x, outh + o0,     outl + o0);
            splitw(O[u][1] * i0 * g0.y, outh + o0 + 1, outl + o0 + 1);
            splitw(O[u][2] * i1 * g1.x, outh + o1,     outl + o1);
            splitw(O[u][3] * i1 * g1.y, outh + o1 + 1, outl + o1 + 1);
        }
    }
}

// ---------------------------------------------------------------------------
// Host launcher
// ---------------------------------------------------------------------------
#define SMEM_ATTN (3 * ABUF)
#define ATTN_GRID 148

extern "C" void kernel_launch(void* const* d_in, const int* in_sizes, int n_in,
                              void* d_out, int out_size) {
    const float* input     = (const float*)d_in[0];
    const float* xl_k_hat  = (const float*)d_in[2];
    const float* xl_v      = (const float*)d_in[3];
    const float* agg_upper = (const float*)d_in[4];
    const float* agg_lower = (const float*)d_in[5];
    const float* W_q       = (const float*)d_in[6];
    const float* W_kvg     = (const float*)d_in[7];
    const float* W_res     = (const float*)d_in[8];
    const float* x_u       = (const float*)d_in[9];
    const float* x_v       = (const float*)d_in[10];
    const float* xl_r      = (const float*)d_in[11];
    const float* codebook  = (const float*)d_in[12];
    float* out = (float*)d_out;

    float *proj, *gate, *rbd, *csq, *cbias;
    unsigned long long* zpk;
    int* ctr;
    bf16 *xt_h, *xt_l, *wall_h, *wall_l, *wrest_h, *wrest_l;
    bf16 *qu_h, *qu_l, *qv_h, *qv_l, *kl_h, *kl_l, *khat_h, *khat_l;
    bf16 *cb_h, *cb_l, *xlr_h, *xlr_l, *xlv_h, *xlv_l, *agu_h, *agu_l;
    bf16 *vvh, *vvl, *wvg_h, *wvg_l;

    cudaGetSymbolAddress((void**)&proj, g_proj);
    cudaGetSymbolAddress((void**)&gate, g_gate);
    cudaGetSymbolAddress((void**)&rbd, g_rbd);
    cudaGetSymbolAddress((void**)&csq, g_csq);
    cudaGetSymbolAddress((void**)&cbias, g_cbias);
    cudaGetSymbolAddress((void**)&zpk, g_zpk);
    cudaGetSymbolAddress((void**)&ctr, g_unit_ctr);
    cudaGetSymbolAddress((void**)&xt_h, g_xt_h);   cudaGetSymbolAddress((void**)&xt_l, g_xt_l);
    cudaGetSymbolAddress((void**)&wall_h, g_wall_h); cudaGetSymbolAddress((void**)&wall_l, g_wall_l);
    cudaGetSymbolAddress((void**)&wrest_h, g_wrest_h); cudaGetSymbolAddress((void**)&wrest_l, g_wrest_l);
    cudaGetSymbolAddress((void**)&qu_h, g_qu_h);   cudaGetSymbolAddress((void**)&qu_l, g_qu_l);
    cudaGetSymbolAddress((void**)&qv_h, g_qv_h);   cudaGetSymbolAddress((void**)&qv_l, g_qv_l);
    cudaGetSymbolAddress((void**)&kl_h, g_kl_h);   cudaGetSymbolAddress((void**)&kl_l, g_kl_l);
    cudaGetSymbolAddress((void**)&khat_h, g_khat_h); cudaGetSymbolAddress((void**)&khat_l, g_khat_l);
    cudaGetSymbolAddress((void**)&cb_h, g_cb_h);   cudaGetSymbolAddress((void**)&cb_l, g_cb_l);
    cudaGetSymbolAddress((void**)&xlr_h, g_xlr_h); cudaGetSymbolAddress((void**)&xlr_l, g_xlr_l);
    cudaGetSymbolAddress((void**)&xlv_h, g_xlv_h); cudaGetSymbolAddress((void**)&xlv_l, g_xlv_l);
    cudaGetSymbolAddress((void**)&agu_h, g_agu_h); cudaGetSymbolAddress((void**)&agu_l, g_agu_l);
    cudaGetSymbolAddress((void**)&vvh, g_vvh);     cudaGetSymbolAddress((void**)&vvl, g_vvl);
    cudaGetSymbolAddress((void**)&wvg_h, g_wvg_h); cudaGetSymbolAddress((void**)&wvg_l, g_wvg_l);

    cudaFuncSetAttribute(attn_kernel, cudaFuncAttributeMaxDynamicSharedMemorySize, SMEM_ATTN);

    // 0. fused preprocessing
    prep_kernel<<<PREP_GRID, 256>>>(W_q, W_kvg, W_res, xl_k_hat, codebook, xl_r, input,
                                    xl_v, agg_upper, agg_lower,
                                    wall_h, wall_l, wrest_h, wrest_l,
                                    khat_h, khat_l, cb_h, cb_l, xlr_h, xlr_l,
                                    xlv_h, xlv_l, agu_h, agu_l,
                                    xt_h, xt_l, csq, cbias, zpk, ctr);

    // 1. fused projection GEMM (Wq | Wkvg), N=4096
    mma_gemm4_kernel<<<dim3(32, 32, 1), 256>>>(xt_h, xt_l, wall_h, wall_l,
                                               proj, 4096, 1024, 1024);

    // 2. per-head LN, biases, silu, v split
    transform_kernel<<<NROWS * CH / 8, 256>>>(proj, x_u, x_v,
                                              qu_h, qu_l, qv_h, qv_l, kl_h, kl_l,
                                              vvh, vvl, gate);

    // 3. merged VQ argmin + BD GEMM
    vqbd_kernel<<<VB_END, 256>>>(kl_h, kl_l, qv_h, qv_l, cb_h, cb_l, xlr_h, xlr_l,
                                 csq, zpk, rbd);

    // 4. fused attention (V via ldmatrix.trans — no vt kernel)
    attn_kernel<<<ATTN_GRID, 256, SMEM_ATTN>>>(qu_h, qu_l, khat_h, khat_l,
                                               cb_h, cb_l, xlv_h, xlv_l, vvh, vvl,
                                               agu_h, agu_l, zpk,
                                               rbd, cbias, gate, ctr, wvg_h, wvg_l);

    // 5. output projection
    mma_gemm4_kernel<<<dim3(8, 32, 1), 256>>>(wvg_h, wvg_l, wrest_h, wrest_l,
                                              out, 1024, 1024, 1024);
}